// round 12
// baseline (speedup 1.0000x reference)
#include <cuda_runtime.h>
#include <cuda_bf16.h>
#include <math.h>

#define BB 128
#define LL 512
#define LAa 8
#define EE 300
#define HH 300
#define G3 900

__device__ __align__(16) int   g_mem_len[BB];
__device__ __align__(16) int   g_asp_len[BB];
__device__ __align__(16) int   g_left_len[BB];
__device__ __align__(16) int   g_right_len[BB];
__device__ __align__(16) float g_qdot[BB];
__device__ __align__(16) float g_attn_l[BB * LL];
__device__ __align__(16) float g_attn_r[BB * LL];
__device__ __align__(16) float g_xp_l[(size_t)BB * LL * G3];
__device__ __align__(16) float g_xp_r[(size_t)BB * LL * G3];
__device__ __align__(16) float g_memory[(size_t)BB * LL * EE];
__device__ __align__(16) float g_kx[(size_t)BB * LL * EE];
__device__ __align__(16) float g_vs[BB * EE];

// cluster-GRU schedule
__device__ int   g_grp_seq[64][4];
__device__ int   g_grp_len[64][4];
__device__ int   g_grp_maxlen[64];
__device__ int   g_grp_side[64];
__device__ int   g_clu_grp[32][2];
__device__ float g_kpad;
// mma A-fragment-packed weights: [(side*4+rank)*15+w][kt][lane][4] b32 (bf16x2)
__device__ __align__(16) unsigned g_Wmma[8 * 15 * 19 * 128];

__device__ __forceinline__ float sigf(float x) { return 1.0f / (1.0f + expf(-x)); }
__device__ __forceinline__ float ftanh(float x) {
    float y; asm("tanh.approx.f32 %0, %1;" : "=f"(y) : "f"(x)); return y;
}
__device__ __forceinline__ float fsig(float x) { return 0.5f * ftanh(0.5f * x) + 0.5f; }

__device__ __forceinline__ unsigned smem_u32(const void* p) {
    unsigned r;
    asm("{ .reg .u64 t; cvta.to.shared.u64 t, %1; cvt.u32.u64 %0, t; }" : "=r"(r) : "l"(p));
    return r;
}
__device__ __forceinline__ unsigned ctarank() {
    unsigned r; asm("mov.u32 %0, %%cluster_ctarank;" : "=r"(r)); return r;
}
#define CLUSTER_SYNC() do { \
    asm volatile("barrier.cluster.arrive.aligned;" ::: "memory"); \
    asm volatile("barrier.cluster.wait.aligned;" ::: "memory"); } while (0)

__device__ __forceinline__ void dst_f32(unsigned laddr, unsigned rk, float v) {
    asm volatile("{ .reg .b32 ra; mapa.shared::cluster.u32 ra, %0, %1; "
                 "st.shared::cluster.b32 [ra], %2; }"
                 :: "r"(laddr), "r"(rk), "r"(__float_as_uint(v)) : "memory");
}

#define MMA16816(c0,c1,c2,c3,a0,a1,a2,a3,b0,b1) \
    asm volatile("mma.sync.aligned.m16n8k16.row.col.f32.bf16.bf16.f32 " \
                 "{%0,%1,%2,%3}, {%4,%5,%6,%7}, {%8,%9}, {%0,%1,%2,%3};" \
                 : "+f"(c0), "+f"(c1), "+f"(c2), "+f"(c3) \
                 : "r"(a0), "r"(a1), "r"(a2), "r"(a3), "r"(b0), "r"(b1))

// split a fp32 pair into (hi bf16x2, lo bf16x2)
__device__ __forceinline__ void split2(float x, float y, unsigned& hi, unsigned& lo) {
    __nv_bfloat16 hx = __float2bfloat16(x);
    __nv_bfloat16 hy = __float2bfloat16(y);
    __nv_bfloat16 lx = __float2bfloat16(x - __bfloat162float(hx));
    __nv_bfloat16 ly = __float2bfloat16(y - __bfloat162float(hy));
    __nv_bfloat162 ph; ph.x = hx; ph.y = hy;
    __nv_bfloat162 pl; pl.x = lx; pl.y = ly;
    hi = *(unsigned*)&ph; lo = *(unsigned*)&pl;
}

// ---------------- K_wpk2: pack W_hh into mma A-fragment layout ----------------
__global__ void k_wpk2(const float* __restrict__ Whh_l, const float* __restrict__ Whh_r)
{
    int tid = threadIdx.x;                 // 128
    int j = tid >> 5, l = tid & 31;
    int gid = l >> 2, tig = l & 3;
    int wkt = blockIdx.x;                  // 0..284
    int w = wkt / 19, kt = wkt % 19;
    int sr = blockIdx.y;                   // 0..7
    int side = sr >> 2, rank = sr & 3;
    const float* W = side ? Whh_r : Whh_l;

    int rl = gid + ((j & 1) ? 8 : 0);
    int k  = kt * 16 + tig * 2 + ((j >= 2) ? 8 : 0);
    int r  = 16 * w + rl;
    float lo = 0.f, hi = 0.f;
    if (r < 225) {
        int G = (r / 75) * 300 + rank * 75 + (r % 75);
        if (k < 300)     lo = W[(size_t)G * HH + k];
        if (k + 1 < 300) hi = W[(size_t)G * HH + k + 1];
    }
    __nv_bfloat162 p = __floats2bfloat162_rn(lo, hi);
    g_Wmma[(size_t)((sr * 15 + w) * 19 + kt) * 128 + l * 4 + j] = *(unsigned*)&p;
}

// ---------------- K0: lengths, attn defaults, aspect mean -> qdot -------------
__global__ void k_init(const int* __restrict__ text, const int* __restrict__ aspi,
                       const int* __restrict__ xl, const int* __restrict__ xr,
                       const float* __restrict__ emb_aspect,
                       const float* __restrict__ w_q, const float* __restrict__ b_q,
                       const float* __restrict__ attn_w,
                       const float* __restrict__ mlp_l_b, const float* __restrict__ mlp_r_b)
{
    int b = blockIdx.x, tid = threadIdx.x;
    int ml = __syncthreads_count(text[b * LL + tid] != 0);
    int ll = __syncthreads_count(xl[b * LL + tid] != 0);
    int rl = __syncthreads_count(xr[b * LL + tid] != 0);
    int al = __syncthreads_count((tid < LAa) && (aspi[b * LAa + tid] != 0));
    if (tid == 0) { g_mem_len[b] = ml; g_left_len[b] = ll; g_right_len[b] = rl; g_asp_len[b] = al; }
    g_attn_l[b * LL + tid] = sigf(mlp_l_b[0]) + 0.5f;
    g_attn_r[b * LL + tid] = sigf(mlp_r_b[0]) + 0.5f;

    __shared__ float s_asp[EE];
    __shared__ float sred[16];
    if (tid < EE) {
        float acc = 0.f;
        #pragma unroll
        for (int a = 0; a < LAa; a++)
            if (a < al) acc += emb_aspect[(size_t)aspi[b * LAa + a] * EE + tid];
        s_asp[tid] = acc / (float)al;
    }
    __syncthreads();
    float val = 0.f;
    if (tid < EE) {
        float acc = b_q[tid];
        const float* wq = w_q + (size_t)tid * EE;
        for (int e = 0; e < EE; e++) acc += s_asp[e] * wq[e];
        val = acc * attn_w[EE + tid];
    }
    #pragma unroll
    for (int o = 16; o > 0; o >>= 1) val += __shfl_xor_sync(0xffffffffu, val, o);
    if ((tid & 31) == 0) sred[tid >> 5] = val;
    __syncthreads();
    if (tid == 0) {
        float s = 0.f;
        #pragma unroll
        for (int w = 0; w < 16; w++) s += sred[w];
        g_qdot[b] = s;
    }
}

// ---------------- K_sched: groups of 4 per side, snake over 32 clusters -------
__global__ void k_sched(const float* __restrict__ b_k, const float* __restrict__ attn_w)
{
    __shared__ float sred[256];
    int i = threadIdx.x;  // 256 threads, 1 block
    float p = 0.f;
    for (int e = i; e < EE; e += 256) p += b_k[e] * attn_w[e];
    sred[i] = p;
    __syncthreads();
    if (i == 0) { float s = 0.f; for (int m = 0; m < 256; m++) s += sred[m]; g_kpad = s; }

    int side = i >> 7, j = i & 127;
    const int* lens = side ? g_right_len : g_left_len;
    int lj = lens[j], r = 0;
    for (int m = 0; m < BB; m++) {
        int lm = lens[m];
        r += (lm > lj) || (lm == lj && m < j);
    }
    int g = side * 32 + (r >> 2);
    g_grp_seq[g][r & 3] = j;
    g_grp_len[g][r & 3] = lj;
    if ((r & 3) == 0) { g_grp_maxlen[g] = lj; g_grp_side[g] = side; }
    __syncthreads();
    if (i < 64) {
        int ml = g_grp_maxlen[i]; int r2 = 0;
        for (int m = 0; m < 64; m++) {
            int lm = g_grp_maxlen[m];
            r2 += (lm > ml) || (lm == ml && m < i);
        }
        int cl = (r2 < 32) ? r2 : 63 - r2;
        g_clu_grp[cl][(r2 < 32) ? 0 : 1] = i;
    }
}

// ---------------- K1: GEMM v5 — split-bf16 HMMA (3-term), 64x64 block ---------
// C = A.W^T + bias with a=a_hi+a_lo, b=b_hi+b_lo; C ≈ hi.hi + hi.lo + lo.hi (fp32 acc)
__global__ void __launch_bounds__(256) k_gemm3(
    const float* __restrict__ Aext, const int* __restrict__ ids,
    const float* __restrict__ W, const float* __restrict__ bias,
    int N, int dst_sel, int limit_sel)
{
    int b = blockIdx.z, m0 = blockIdx.y * 64, n0 = blockIdx.x * 64;
    int lim = (limit_sel == 1) ? g_left_len[b] : (limit_sel == 2) ? g_right_len[b]
            : (limit_sel == 3) ? g_mem_len[b] : LL;
    if (m0 >= lim) return;

    float* C = (dst_sel == 0) ? g_xp_l : (dst_sel == 1) ? g_xp_r : g_kx;
    float* Cb = C + (size_t)b * LL * N;
    const int* bids = ids ? (ids + (size_t)b * LL) : (const int*)0;

    extern __shared__ __align__(16) __nv_bfloat16 smem[];
    __nv_bfloat16* Ah = smem;               // [64][312]
    __nv_bfloat16* Al = smem + 1 * 64 * 312;
    __nv_bfloat16* Bh = smem + 2 * 64 * 312;
    __nv_bfloat16* Bl = smem + 3 * 64 * 312;

    int tid = threadIdx.x, lane = tid & 31, wid = tid >> 5;
    int gid = lane >> 2, tig = lane & 3;

    // zero k-pad region (b32 words 150..155 of each row)
    for (int idx = tid; idx < 64 * 6; idx += 256) {
        int row = idx / 6, w = idx % 6;
        ((unsigned*)(Ah + row * 312))[150 + w] = 0u;
        ((unsigned*)(Al + row * 312))[150 + w] = 0u;
        ((unsigned*)(Bh + row * 312))[150 + w] = 0u;
        ((unsigned*)(Bl + row * 312))[150 + w] = 0u;
    }
    // stage A split
    for (int idx = tid; idx < 64 * 75; idx += 256) {
        int row = idx / 75, c4 = (idx % 75) * 4;
        int gm = m0 + row;
        const float* ar;
        if (bids) ar = Aext + (size_t)bids[gm] * EE;
        else      ar = g_memory + ((size_t)b * LL + gm) * EE;
        float4 v = *(const float4*)(ar + c4);
        unsigned h0, l0, h1, l1;
        split2(v.x, v.y, h0, l0);
        split2(v.z, v.w, h1, l1);
        unsigned* dh = (unsigned*)(Ah + row * 312 + c4);
        unsigned* dl = (unsigned*)(Al + row * 312 + c4);
        dh[0] = h0; dh[1] = h1; dl[0] = l0; dl[1] = l1;
    }
    // stage B split
    for (int idx = tid; idx < 64 * 75; idx += 256) {
        int row = idx / 75, c4 = (idx % 75) * 4;
        int gn = n0 + row;
        unsigned* dh = (unsigned*)(Bh + row * 312 + c4);
        unsigned* dl = (unsigned*)(Bl + row * 312 + c4);
        if (gn < N) {
            float4 v = *(const float4*)(W + (size_t)gn * EE + c4);
            unsigned h0, l0, h1, l1;
            split2(v.x, v.y, h0, l0);
            split2(v.z, v.w, h1, l1);
            dh[0] = h0; dh[1] = h1; dl[0] = l0; dl[1] = l1;
        } else {
            dh[0] = 0u; dh[1] = 0u; dl[0] = 0u; dl[1] = 0u;
        }
    }
    __syncthreads();

    int wm = wid >> 1, wn = wid & 1;
    const unsigned* AH = (const unsigned*)Ah;   // row stride 156 words
    const unsigned* AL = (const unsigned*)Al;
    const unsigned* BH = (const unsigned*)Bh;
    const unsigned* BL = (const unsigned*)Bl;
    float c[4][4];
    #pragma unroll
    for (int t = 0; t < 4; t++)
        #pragma unroll
        for (int r = 0; r < 4; r++) c[t][r] = 0.f;

    int arow0 = (wm * 16 + gid) * 156;
    int arow1 = arow0 + 8 * 156;
    #pragma unroll
    for (int kt = 0; kt < 19; kt++) {
        int ka = kt * 8 + tig;
        unsigned ah0 = AH[arow0 + ka], ah1 = AH[arow1 + ka];
        unsigned ah2 = AH[arow0 + ka + 4], ah3 = AH[arow1 + ka + 4];
        unsigned al0 = AL[arow0 + ka], al1 = AL[arow1 + ka];
        unsigned al2 = AL[arow0 + ka + 4], al3 = AL[arow1 + ka + 4];
        #pragma unroll
        for (int t = 0; t < 4; t++) {
            int nr = (wn * 32 + t * 8 + gid) * 156;
            unsigned bh0 = BH[nr + ka], bh1 = BH[nr + ka + 4];
            unsigned bl0 = BL[nr + ka], bl1 = BL[nr + ka + 4];
            MMA16816(c[t][0], c[t][1], c[t][2], c[t][3], ah0, ah1, ah2, ah3, bh0, bh1);
            MMA16816(c[t][0], c[t][1], c[t][2], c[t][3], ah0, ah1, ah2, ah3, bl0, bl1);
            MMA16816(c[t][0], c[t][1], c[t][2], c[t][3], al0, al1, al2, al3, bh0, bh1);
        }
    }
    #pragma unroll
    for (int t = 0; t < 4; t++) {
        int on = n0 + wn * 32 + t * 8 + tig * 2;
        int om = m0 + wm * 16 + gid;
        if (on < N) {
            float bi = bias[on];
            Cb[(size_t)om * N + on]       = c[t][0] + bi;
            Cb[(size_t)(om + 8) * N + on] = c[t][2] + bi;
        }
        if (on + 1 < N) {
            float bi = bias[on + 1];
            Cb[(size_t)om * N + on + 1]       = c[t][1] + bi;
            Cb[(size_t)(om + 8) * N + on + 1] = c[t][3] + bi;
        }
    }
}

// ---------------- K2: cluster-4 GRU, tensor-core GEMV (HMMA) — R9 -------------
__global__ void __launch_bounds__(512, 1) __cluster_dims__(4, 1, 1)
k_gruT(const float* __restrict__ bhh_l, const float* __restrict__ bhh_r,
       const float* __restrict__ mlpw_l, const float* __restrict__ mlpb_l,
       const float* __restrict__ mlpw_r, const float* __restrict__ mlpb_r)
{
    __shared__ __align__(16) float s_h[2][4][304];
    __shared__ __align__(16) unsigned hb[8 * 156];
    __shared__ __align__(16) float s_gate[240][4];
    __shared__ float s_red[320];
    __shared__ float s_partial[32];

    int tid = threadIdx.x, lane = tid & 31, wid = tid >> 5;
    int gid = lane >> 2, tig = lane & 3;
    unsigned rank = ctarank();
    int c = blockIdx.x >> 2;

    for (int gi = 0; gi < 2; gi++) {
        int grp  = g_clu_grp[c][gi];
        int side = g_grp_side[grp];
        int tmax = g_grp_maxlen[grp];
        const float* bhh  = side ? bhh_r : bhh_l;
        const float* mlpw = side ? mlpw_r : mlpw_l;
        float mbb = side ? mlpb_r[0] : mlpb_l[0];
        const float* xp = side ? g_xp_r : g_xp_l;
        float* attn = side ? g_attn_r : g_attn_l;
        int seqv[4], lenv[4];
        #pragma unroll
        for (int s = 0; s < 4; s++) { seqv[s] = g_grp_seq[grp][s]; lenv[s] = g_grp_len[grp][s]; }

        for (int i = tid; i < 2 * 4 * 304; i += 512) ((float*)s_h)[i] = 0.f;
        for (int i = tid; i < 8 * 156; i += 512) hb[i] = 0u;

        unsigned a[19][4];
        if (wid < 15) {
            const uint4* src = (const uint4*)g_Wmma
                             + (size_t)(((side * 4 + (int)rank) * 15 + wid) * 19) * 32 + lane;
            #pragma unroll
            for (int kt = 0; kt < 19; kt++) {
                uint4 v = src[kt * 32];
                a[kt][0] = v.x; a[kt][1] = v.y; a[kt][2] = v.z; a[kt][3] = v.w;
            }
        }

        int sB = tid / 75, uB = tid % 75, GB = (int)rank * 75 + uB;
        float bhr = 0.f, bhz = 0.f, bhn = 0.f, wm = 0.f, h_reg = 0.f;
        const float* xpb = 0;
        if (tid < 300) {
            bhr = bhh[GB]; bhz = bhh[300 + GB]; bhn = bhh[600 + GB]; wm = mlpw[GB];
            xpb = xp + (size_t)seqv[sB] * LL * G3;
        }
        unsigned hl0 = 0, hl1 = 0;
        if (tid < 300) {
            hl0 = smem_u32(&s_h[0][sB][GB]);
            hl1 = smem_u32(&s_h[1][sB][GB]);
        }
        __syncthreads();
        CLUSTER_SYNC();

        int buf = 0;
        for (int t = 0; t < tmax; t++) {
            if (t > 0 && rank == 0 && tid < 4) {
                float* pp = s_partial + (buf ^ 1) * 16;
                float sum = pp[tid] + pp[4 + tid] + pp[8 + tid] + pp[12 + tid];
                if (t - 1 < lenv[tid]) attn[seqv[tid] * LL + (t - 1)] = fsig(sum + mbb) + 0.5f;
            }
            float gr = 0.f, gz = 0.f, gn2 = 0.f;
            if (tid < 300) {
                const float* xr = xpb + (size_t)t * G3;
                gr = xr[GB]; gz = xr[300 + GB]; gn2 = xr[600 + GB];
            }
            if (tid < 300) {
                __nv_bfloat16* hh = (__nv_bfloat16*)hb;
                #pragma unroll
                for (int s = 0; s < 4; s++)
                    hh[s * 312 + tid] = __float2bfloat16(s_h[buf][s][tid]);
            }
            __syncthreads();
            if (wid < 15) {
                float c0 = 0.f, c1 = 0.f, c2 = 0.f, c3 = 0.f;
                float d0 = 0.f, d1 = 0.f, d2 = 0.f, d3 = 0.f;
                #pragma unroll
                for (int kt = 0; kt < 19; kt += 2) {
                    unsigned b0 = hb[gid * 156 + kt * 8 + tig];
                    unsigned b1 = hb[gid * 156 + kt * 8 + tig + 4];
                    MMA16816(c0, c1, c2, c3, a[kt][0], a[kt][1], a[kt][2], a[kt][3], b0, b1);
                    if (kt + 1 < 19) {
                        unsigned e0 = hb[gid * 156 + (kt + 1) * 8 + tig];
                        unsigned e1 = hb[gid * 156 + (kt + 1) * 8 + tig + 4];
                        MMA16816(d0, d1, d2, d3, a[kt+1][0], a[kt+1][1], a[kt+1][2], a[kt+1][3], e0, e1);
                    }
                }
                c0 += d0; c1 += d1; c2 += d2; c3 += d3;
                if (tig < 2) {
                    int r0 = wid * 16 + gid;
                    *(float2*)&s_gate[r0][2 * tig]     = make_float2(c0, c1);
                    *(float2*)&s_gate[r0 + 8][2 * tig] = make_float2(c2, c3);
                }
            }
            __syncthreads();
            if (tid < 300) {
                float rp = s_gate[uB][sB];
                float zp = s_gate[75 + uB][sB];
                float np = s_gate[150 + uB][sB];
                float r = fsig(gr + rp + bhr);
                float z = fsig(gz + zp + bhz);
                float n = ftanh(gn2 + r * (np + bhn));
                h_reg = (1.f - z) * n + z * h_reg;
                unsigned la = buf ? hl0 : hl1;
                #pragma unroll
                for (unsigned rk = 0; rk < 4; rk++) dst_f32(la, rk, h_reg);
                s_red[sB * 80 + uB] = h_reg * wm;
            }
            __syncthreads();
            if (wid < 4) {
                float v = s_red[wid * 80 + lane];
                if (lane < 43) v += s_red[wid * 80 + lane + 32];
                if (lane < 11) v += s_red[wid * 80 + lane + 64];
                #pragma unroll
                for (int o = 16; o > 0; o >>= 1) v += __shfl_xor_sync(0xffffffffu, v, o);
                if (lane == 0) {
                    unsigned la = smem_u32(&s_partial[buf * 16 + (int)rank * 4 + wid]);
                    dst_f32(la, 0, v);
                }
            }
            CLUSTER_SYNC();
            buf ^= 1;
        }
        if (rank == 0 && tid < 4) {
            float* pp = s_partial + (buf ^ 1) * 16;
            float sum = pp[tid] + pp[4 + tid] + pp[8 + tid] + pp[12 + tid];
            if (tmax - 1 < lenv[tid]) attn[seqv[tid] * LL + (tmax - 1)] = fsig(sum + mbb) + 0.5f;
        }
        __syncthreads();
        CLUSTER_SYNC();
    }
}

// ---------------- K3: memory = emb[text] * scale ------------------------------
__global__ void k_mem(const int* __restrict__ text, const float* __restrict__ emb)
{
    int l = blockIdx.x, b = blockIdx.y, tid = threadIdx.x;
    if (tid >= EE) return;
    float* row = g_memory + ((size_t)b * LL + l) * EE;
    int ml = g_mem_len[b];
    if (l >= ml) { row[tid] = 0.f; return; }
    int astart = g_left_len[b] - g_asp_len[b];
    int aend = g_left_len[b];
    float al = g_attn_l[b * LL + l];
    int ridx = min(max(l - astart, 0), LL - 1);
    float arv = g_attn_r[b * LL + ridx];
    float sc = (l < astart) ? al : ((l < aend) ? (al + arv) : arv);
    int id = text[b * LL + l];
    row[tid] = emb[(size_t)id * EE + tid] * sc;
}

// ---------------- K4: v_s -----------------------------------------------------
__global__ void k_vs()
{
    int b = blockIdx.x, tid = threadIdx.x;
    if (tid >= EE) return;
    float acc = 0.f;
    const float* p = g_memory + (size_t)b * LL * EE + tid;
    int ml = g_mem_len[b];
    for (int l = 0; l < ml; l++) acc += p[(size_t)l * EE];
    g_vs[b * EE + tid] = acc / (float)ml;
}

// ---------------- K5: score->softmax->v_ts->proj->mlp->dense ------------------
__global__ void __launch_bounds__(512) k_tail(
    const float* __restrict__ attn_w, const float* __restrict__ b_k,
    const float* __restrict__ proj_w, const float* __restrict__ proj_b,
    const float* __restrict__ mlp_w, const float* __restrict__ mlp_b,
    const float* __restrict__ dense_w, const float* __restrict__ dense_b,
    float* __restrict__ out)
{
    int b = blockIdx.x, tid = threadIdx.x, lane = tid & 31, wid = tid >> 5;
    __shared__ float s_aw[EE];
    __shared__ float s_sc[LL];
    __shared__ float smax[16], ssum[16];
    __shared__ float s_v[EE], s_v2[EE];
    const float* kxb = g_kx + (size_t)b * LL * EE;
    int ml = g_mem_len[b];
    if (tid < EE) s_aw[tid] = attn_w[tid];
    __syncthreads();
    float qd = g_qdot[b];
    float sc_pad = tanhf(g_kpad + qd);
    for (int l = wid; l < ml; l += 16) {
        const float* row = kxb + (size_t)l * EE;
        float acc = 0.f;
        for (int e = lane; e < EE; e += 32) acc += row[e] * s_aw[e];
        #pragma unroll
        for (int o = 16; o > 0; o >>= 1) acc += __shfl_xor_sync(0xffffffffu, acc, o);
        if (lane == 0) s_sc[l] = tanhf(acc + qd);
    }
    __syncthreads();
    float x = (tid < ml) ? s_sc[tid] : sc_pad;
    float m = x;
    #pragma unroll
    for (int o = 16; o > 0; o >>= 1) m = fmaxf(m, __shfl_xor_sync(0xffffffffu, m, o));
    if (lane == 0) smax[wid] = m;
    __syncthreads();
    float bm = smax[0];
    #pragma unroll
    for (int w = 1; w < 16; w++) bm = fmaxf(bm, smax[w]);
    float p = expf(x - bm);
    float sm = p;
    #pragma unroll
    for (int o = 16; o > 0; o >>= 1) sm += __shfl_xor_sync(0xffffffffu, sm, o);
    if (lane == 0) ssum[wid] = sm;
    __syncthreads();
    float tot = 0.f;
    #pragma unroll
    for (int w = 0; w < 16; w++) tot += ssum[w];
    s_sc[tid] = p / tot;
    __syncthreads();
    float pad_prob = expf(sc_pad - bm) / tot;
    if (tid < EE) {
        float acc = (float)(LL - ml) * pad_prob * b_k[tid];
        for (int l = 0; l < ml; l++) acc += s_sc[l] * kxb[(size_t)l * EE + tid];
        s_v[tid] = acc;
    }
    __syncthreads();
    if (tid < EE) {
        float acc = proj_b[tid];
        const float* w = proj_w + (size_t)tid * EE;
        for (int e = 0; e < EE; e++) acc += s_v[e] * w[e];
        s_v2[tid] = acc + g_vs[b * EE + tid];
    }
    __syncthreads();
    if (tid < EE) {
        float acc = mlp_b[tid];
        const float* w = mlp_w + (size_t)tid * EE;
        for (int e = 0; e < EE; e++) acc += s_v2[e] * w[e];
        s_v[tid] = tanhf(acc);
    }
    __syncthreads();
    if (wid < 3) {
        const float* w = dense_w + (size_t)wid * EE;
        float acc = 0.f;
        for (int e = lane; e < EE; e += 32) acc += s_v[e] * w[e];
        #pragma unroll
        for (int o = 16; o > 0; o >>= 1) acc += __shfl_xor_sync(0xffffffffu, acc, o);
        if (lane == 0) out[b * 3 + wid] = acc + dense_b[wid];
    }
}

extern "C" void kernel_launch(void* const* d_in, const int* in_sizes, int n_in,
                              void* d_out, int out_size)
{
    const int*   text  = (const int*)d_in[0];
    const int*   aspi  = (const int*)d_in[1];
    const int*   xl    = (const int*)d_in[2];
    const int*   xr    = (const int*)d_in[3];
    const float* emb   = (const float*)d_in[4];
    const float* emb_a = (const float*)d_in[5];
    const float* Wih_l = (const float*)d_in[6];
    const float* Whh_l = (const float*)d_in[7];
    const float* bih_l = (const float*)d_in[8];
    const float* bhh_l = (const float*)d_in[9];
    const float* Wih_r = (const float*)d_in[10];
    const float* Whh_r = (const float*)d_in[11];
    const float* bih_r = (const float*)d_in[12];
    const float* bhh_r = (const float*)d_in[13];
    const float* mlw_l = (const float*)d_in[14];
    const float* mlb_l = (const float*)d_in[15];
    const float* mlw_r = (const float*)d_in[16];
    const float* mlb_r = (const float*)d_in[17];
    const float* w_k   = (const float*)d_in[18];
    const float* b_k   = (const float*)d_in[19];
    const float* w_q   = (const float*)d_in[20];
    const float* b_q   = (const float*)d_in[21];
    const float* aw    = (const float*)d_in[22];
    const float* pw    = (const float*)d_in[23];
    const float* pb    = (const float*)d_in[24];
    const float* mw    = (const float*)d_in[25];
    const float* mb    = (const float*)d_in[26];
    const float* dw    = (const float*)d_in[27];
    const float* db    = (const float*)d_in[28];
    float* out = (float*)d_out;

    const int GEMM_SMEM = 4 * 64 * 312 * 2;   // 159744 B
    cudaFuncSetAttribute(k_gemm3, cudaFuncAttributeMaxDynamicSharedMemorySize, GEMM_SMEM);

    k_wpk2<<<dim3(285, 8), 128>>>(Whh_l, Whh_r);
    k_init<<<BB, 512>>>(text, aspi, xl, xr, emb_a, w_q, b_q, aw, mlb_l, mlb_r);
    k_sched<<<1, 256>>>(b_k, aw);

    dim3 gx((G3 + 63) / 64, LL / 64, BB);
    k_gemm3<<<gx, 256, GEMM_SMEM>>>(emb, xl, Wih_l, bih_l, G3, 0, 1);
    k_gemm3<<<gx, 256, GEMM_SMEM>>>(emb, xr, Wih_r, bih_r, G3, 1, 2);

    k_gruT<<<BB, 512>>>(bhh_l, bhh_r, mlw_l, mlb_l, mlw_r, mlb_r);

    k_mem<<<dim3(LL, BB), 320>>>(text, emb);
    k_vs<<<BB, 320>>>();

    dim3 gk((EE + 63) / 64, LL / 64, BB);
    k_gemm3<<<gk, 256, GEMM_SMEM>>>(emb, (const int*)0, w_k, b_k, EE, 2, 3);

    k_tail<<<BB, 512>>>(aw, b_k, pw, pb, mw, mb, dw, db, out);
}

// round 13
// speedup vs baseline: 1.5561x; 1.5561x over previous
#include <cuda_runtime.h>
#include <cuda_bf16.h>
#include <cuda_fp16.h>
#include <math.h>

#define BB 128
#define LL 512
#define LAa 8
#define EE 300
#define HH 300
#define G3 900

__device__ __align__(16) int   g_mem_len[BB];
__device__ __align__(16) int   g_asp_len[BB];
__device__ __align__(16) int   g_left_len[BB];
__device__ __align__(16) int   g_right_len[BB];
__device__ __align__(16) float g_qdot[BB];
__device__ __align__(16) float g_attn_l[BB * LL];
__device__ __align__(16) float g_attn_r[BB * LL];
__device__ __align__(16) float g_xp_l[(size_t)BB * LL * G3];
__device__ __align__(16) float g_xp_r[(size_t)BB * LL * G3];
__device__ __align__(16) float g_memory[(size_t)BB * LL * EE];
__device__ __align__(16) float g_kx[(size_t)BB * LL * EE];
__device__ __align__(16) float g_vs[BB * EE];

// cluster-GRU schedule
__device__ int   g_grp_seq[64][4];
__device__ int   g_grp_len[64][4];
__device__ int   g_grp_maxlen[64];
__device__ int   g_grp_side[64];
__device__ int   g_clu_grp[32][2];
__device__ float g_kpad;
// mma A-fragment-packed weights: [(side*4+rank)*15+w][kt][lane][4] b32 (bf16x2)
__device__ __align__(16) unsigned g_Wmma[8 * 15 * 19 * 128];

__device__ __forceinline__ float sigf(float x) { return 1.0f / (1.0f + expf(-x)); }
__device__ __forceinline__ float ftanh(float x) {
    float y; asm("tanh.approx.f32 %0, %1;" : "=f"(y) : "f"(x)); return y;
}
__device__ __forceinline__ float fsig(float x) { return 0.5f * ftanh(0.5f * x) + 0.5f; }

__device__ __forceinline__ unsigned smem_u32(const void* p) {
    unsigned r;
    asm("{ .reg .u64 t; cvta.to.shared.u64 t, %1; cvt.u32.u64 %0, t; }" : "=r"(r) : "l"(p));
    return r;
}
__device__ __forceinline__ unsigned ctarank() {
    unsigned r; asm("mov.u32 %0, %%cluster_ctarank;" : "=r"(r)); return r;
}
#define CLUSTER_SYNC() do { \
    asm volatile("barrier.cluster.arrive.aligned;" ::: "memory"); \
    asm volatile("barrier.cluster.wait.aligned;" ::: "memory"); } while (0)

__device__ __forceinline__ void dst_f32(unsigned laddr, unsigned rk, float v) {
    asm volatile("{ .reg .b32 ra; mapa.shared::cluster.u32 ra, %0, %1; "
                 "st.shared::cluster.b32 [ra], %2; }"
                 :: "r"(laddr), "r"(rk), "r"(__float_as_uint(v)) : "memory");
}

#define MMA16816(c0,c1,c2,c3,a0,a1,a2,a3,b0,b1) \
    asm volatile("mma.sync.aligned.m16n8k16.row.col.f32.bf16.bf16.f32 " \
                 "{%0,%1,%2,%3}, {%4,%5,%6,%7}, {%8,%9}, {%0,%1,%2,%3};" \
                 : "+f"(c0), "+f"(c1), "+f"(c2), "+f"(c3) \
                 : "r"(a0), "r"(a1), "r"(a2), "r"(a3), "r"(b0), "r"(b1))

#define MMAH16816(c0,c1,c2,c3,a0,a1,a2,a3,b0,b1) \
    asm volatile("mma.sync.aligned.m16n8k16.row.col.f32.f16.f16.f32 " \
                 "{%0,%1,%2,%3}, {%4,%5,%6,%7}, {%8,%9}, {%0,%1,%2,%3};" \
                 : "+f"(c0), "+f"(c1), "+f"(c2), "+f"(c3) \
                 : "r"(a0), "r"(a1), "r"(a2), "r"(a3), "r"(b0), "r"(b1))

// ---------------- K_wpk2: pack W_hh into mma A-fragment layout (bf16, GRU) ----
__global__ void k_wpk2(const float* __restrict__ Whh_l, const float* __restrict__ Whh_r)
{
    int tid = threadIdx.x;                 // 128
    int j = tid >> 5, l = tid & 31;
    int gid = l >> 2, tig = l & 3;
    int wkt = blockIdx.x;                  // 0..284
    int w = wkt / 19, kt = wkt % 19;
    int sr = blockIdx.y;                   // 0..7
    int side = sr >> 2, rank = sr & 3;
    const float* W = side ? Whh_r : Whh_l;

    int rl = gid + ((j & 1) ? 8 : 0);
    int k  = kt * 16 + tig * 2 + ((j >= 2) ? 8 : 0);
    int r  = 16 * w + rl;
    float lo = 0.f, hi = 0.f;
    if (r < 225) {
        int G = (r / 75) * 300 + rank * 75 + (r % 75);
        if (k < 300)     lo = W[(size_t)G * HH + k];
        if (k + 1 < 300) hi = W[(size_t)G * HH + k + 1];
    }
    __nv_bfloat162 p = __floats2bfloat162_rn(lo, hi);
    g_Wmma[(size_t)((sr * 15 + w) * 19 + kt) * 128 + l * 4 + j] = *(unsigned*)&p;
}

// ---------------- K0: lengths, attn defaults, aspect mean -> qdot -------------
__global__ void k_init(const int* __restrict__ text, const int* __restrict__ aspi,
                       const int* __restrict__ xl, const int* __restrict__ xr,
                       const float* __restrict__ emb_aspect,
                       const float* __restrict__ w_q, const float* __restrict__ b_q,
                       const float* __restrict__ attn_w,
                       const float* __restrict__ mlp_l_b, const float* __restrict__ mlp_r_b)
{
    int b = blockIdx.x, tid = threadIdx.x;
    int ml = __syncthreads_count(text[b * LL + tid] != 0);
    int ll = __syncthreads_count(xl[b * LL + tid] != 0);
    int rl = __syncthreads_count(xr[b * LL + tid] != 0);
    int al = __syncthreads_count((tid < LAa) && (aspi[b * LAa + tid] != 0));
    if (tid == 0) { g_mem_len[b] = ml; g_left_len[b] = ll; g_right_len[b] = rl; g_asp_len[b] = al; }
    g_attn_l[b * LL + tid] = sigf(mlp_l_b[0]) + 0.5f;
    g_attn_r[b * LL + tid] = sigf(mlp_r_b[0]) + 0.5f;

    __shared__ float s_asp[EE];
    __shared__ float sred[16];
    if (tid < EE) {
        float acc = 0.f;
        #pragma unroll
        for (int a = 0; a < LAa; a++)
            if (a < al) acc += emb_aspect[(size_t)aspi[b * LAa + a] * EE + tid];
        s_asp[tid] = acc / (float)al;
    }
    __syncthreads();
    float val = 0.f;
    if (tid < EE) {
        float acc = b_q[tid];
        const float* wq = w_q + (size_t)tid * EE;
        for (int e = 0; e < EE; e++) acc += s_asp[e] * wq[e];
        val = acc * attn_w[EE + tid];
    }
    #pragma unroll
    for (int o = 16; o > 0; o >>= 1) val += __shfl_xor_sync(0xffffffffu, val, o);
    if ((tid & 31) == 0) sred[tid >> 5] = val;
    __syncthreads();
    if (tid == 0) {
        float s = 0.f;
        #pragma unroll
        for (int w = 0; w < 16; w++) s += sred[w];
        g_qdot[b] = s;
    }
}

// ---------------- K_sched: groups of 4 per side, snake over 32 clusters -------
__global__ void k_sched(const float* __restrict__ b_k, const float* __restrict__ attn_w)
{
    __shared__ float sred[256];
    int i = threadIdx.x;  // 256 threads, 1 block
    float p = 0.f;
    for (int e = i; e < EE; e += 256) p += b_k[e] * attn_w[e];
    sred[i] = p;
    __syncthreads();
    if (i == 0) { float s = 0.f; for (int m = 0; m < 256; m++) s += sred[m]; g_kpad = s; }

    int side = i >> 7, j = i & 127;
    const int* lens = side ? g_right_len : g_left_len;
    int lj = lens[j], r = 0;
    for (int m = 0; m < BB; m++) {
        int lm = lens[m];
        r += (lm > lj) || (lm == lj && m < j);
    }
    int g = side * 32 + (r >> 2);
    g_grp_seq[g][r & 3] = j;
    g_grp_len[g][r & 3] = lj;
    if ((r & 3) == 0) { g_grp_maxlen[g] = lj; g_grp_side[g] = side; }
    __syncthreads();
    if (i < 64) {
        int ml = g_grp_maxlen[i]; int r2 = 0;
        for (int m = 0; m < 64; m++) {
            int lm = g_grp_maxlen[m];
            r2 += (lm > ml) || (lm == ml && m < i);
        }
        int cl = (r2 < 32) ? r2 : 63 - r2;
        g_clu_grp[cl][(r2 < 32) ? 0 : 1] = i;
    }
}

// ---------------- K1: GEMM v6 — fp16 HMMA single-term, 64x64, 2 CTA/SM --------
// fp16 inputs (11 mantissa bits), fp32 accumulate. Layout validated in R10/R11.
__global__ void __launch_bounds__(256, 2) k_gemm3(
    const float* __restrict__ Aext, const int* __restrict__ ids,
    const float* __restrict__ W, const float* __restrict__ bias,
    int N, int dst_sel, int limit_sel)
{
    int b = blockIdx.z, m0 = blockIdx.y * 64, n0 = blockIdx.x * 64;
    int lim = (limit_sel == 1) ? g_left_len[b] : (limit_sel == 2) ? g_right_len[b]
            : (limit_sel == 3) ? g_mem_len[b] : LL;
    if (m0 >= lim) return;

    float* C = (dst_sel == 0) ? g_xp_l : (dst_sel == 1) ? g_xp_r : g_kx;
    float* Cb = C + (size_t)b * LL * N;
    const int* bids = ids ? (ids + (size_t)b * LL) : (const int*)0;

    extern __shared__ __align__(16) __half smem[];
    __half* As = smem;              // [64][312]
    __half* Bs = smem + 64 * 312;   // [64][312]

    int tid = threadIdx.x, lane = tid & 31, wid = tid >> 5;
    int gid = lane >> 2, tig = lane & 3;

    // zero k-pad region (b32 words 150..155 of each row)
    for (int idx = tid; idx < 64 * 6; idx += 256) {
        int row = idx / 6, w = idx % 6;
        ((unsigned*)(As + row * 312))[150 + w] = 0u;
        ((unsigned*)(Bs + row * 312))[150 + w] = 0u;
    }
    // stage A as fp16
    for (int idx = tid; idx < 64 * 75; idx += 256) {
        int row = idx / 75, c4 = (idx % 75) * 4;
        int gm = m0 + row;
        const float* ar;
        if (bids) ar = Aext + (size_t)bids[gm] * EE;
        else      ar = g_memory + ((size_t)b * LL + gm) * EE;
        float4 v = *(const float4*)(ar + c4);
        __half2 p0 = __floats2half2_rn(v.x, v.y);
        __half2 p1 = __floats2half2_rn(v.z, v.w);
        unsigned* dst = (unsigned*)(As + row * 312 + c4);
        dst[0] = *(unsigned*)&p0; dst[1] = *(unsigned*)&p1;
    }
    // stage B as fp16
    for (int idx = tid; idx < 64 * 75; idx += 256) {
        int row = idx / 75, c4 = (idx % 75) * 4;
        int gn = n0 + row;
        unsigned* dst = (unsigned*)(Bs + row * 312 + c4);
        if (gn < N) {
            float4 v = *(const float4*)(W + (size_t)gn * EE + c4);
            __half2 p0 = __floats2half2_rn(v.x, v.y);
            __half2 p1 = __floats2half2_rn(v.z, v.w);
            dst[0] = *(unsigned*)&p0; dst[1] = *(unsigned*)&p1;
        } else {
            dst[0] = 0u; dst[1] = 0u;
        }
    }
    __syncthreads();

    int wm = wid >> 1, wn = wid & 1;
    const unsigned* A32 = (const unsigned*)As;   // row stride 156 words
    const unsigned* B32 = (const unsigned*)Bs;
    float c[4][4];
    #pragma unroll
    for (int t = 0; t < 4; t++)
        #pragma unroll
        for (int r = 0; r < 4; r++) c[t][r] = 0.f;

    int arow0 = (wm * 16 + gid) * 156;
    int arow1 = arow0 + 8 * 156;
    #pragma unroll
    for (int kt = 0; kt < 19; kt++) {
        int ka = kt * 8 + tig;
        unsigned a0 = A32[arow0 + ka];
        unsigned a1 = A32[arow1 + ka];
        unsigned a2 = A32[arow0 + ka + 4];
        unsigned a3 = A32[arow1 + ka + 4];
        #pragma unroll
        for (int t = 0; t < 4; t++) {
            int nr = (wn * 32 + t * 8 + gid) * 156;
            unsigned b0 = B32[nr + ka];
            unsigned b1 = B32[nr + ka + 4];
            MMAH16816(c[t][0], c[t][1], c[t][2], c[t][3], a0, a1, a2, a3, b0, b1);
        }
    }
    #pragma unroll
    for (int t = 0; t < 4; t++) {
        int on = n0 + wn * 32 + t * 8 + tig * 2;
        int om = m0 + wm * 16 + gid;
        if (on < N) {
            float bi = bias[on];
            Cb[(size_t)om * N + on]       = c[t][0] + bi;
            Cb[(size_t)(om + 8) * N + on] = c[t][2] + bi;
        }
        if (on + 1 < N) {
            float bi = bias[on + 1];
            Cb[(size_t)om * N + on + 1]       = c[t][1] + bi;
            Cb[(size_t)(om + 8) * N + on + 1] = c[t][3] + bi;
        }
    }
}

// ---------------- K2: cluster-4 GRU, tensor-core GEMV (HMMA bf16) — R9 --------
__global__ void __launch_bounds__(512, 1) __cluster_dims__(4, 1, 1)
k_gruT(const float* __restrict__ bhh_l, const float* __restrict__ bhh_r,
       const float* __restrict__ mlpw_l, const float* __restrict__ mlpb_l,
       const float* __restrict__ mlpw_r, const float* __restrict__ mlpb_r)
{
    __shared__ __align__(16) float s_h[2][4][304];
    __shared__ __align__(16) unsigned hb[8 * 156];
    __shared__ __align__(16) float s_gate[240][4];
    __shared__ float s_red[320];
    __shared__ float s_partial[32];

    int tid = threadIdx.x, lane = tid & 31, wid = tid >> 5;
    int gid = lane >> 2, tig = lane & 3;
    unsigned rank = ctarank();
    int c = blockIdx.x >> 2;

    for (int gi = 0; gi < 2; gi++) {
        int grp  = g_clu_grp[c][gi];
        int side = g_grp_side[grp];
        int tmax = g_grp_maxlen[grp];
        const float* bhh  = side ? bhh_r : bhh_l;
        const float* mlpw = side ? mlpw_r : mlpw_l;
        float mbb = side ? mlpb_r[0] : mlpb_l[0];
        const float* xp = side ? g_xp_r : g_xp_l;
        float* attn = side ? g_attn_r : g_attn_l;
        int seqv[4], lenv[4];
        #pragma unroll
        for (int s = 0; s < 4; s++) { seqv[s] = g_grp_seq[grp][s]; lenv[s] = g_grp_len[grp][s]; }

        for (int i = tid; i < 2 * 4 * 304; i += 512) ((float*)s_h)[i] = 0.f;
        for (int i = tid; i < 8 * 156; i += 512) hb[i] = 0u;

        unsigned a[19][4];
        if (wid < 15) {
            const uint4* src = (const uint4*)g_Wmma
                             + (size_t)(((side * 4 + (int)rank) * 15 + wid) * 19) * 32 + lane;
            #pragma unroll
            for (int kt = 0; kt < 19; kt++) {
                uint4 v = src[kt * 32];
                a[kt][0] = v.x; a[kt][1] = v.y; a[kt][2] = v.z; a[kt][3] = v.w;
            }
        }

        int sB = tid / 75, uB = tid % 75, GB = (int)rank * 75 + uB;
        float bhr = 0.f, bhz = 0.f, bhn = 0.f, wm = 0.f, h_reg = 0.f;
        const float* xpb = 0;
        if (tid < 300) {
            bhr = bhh[GB]; bhz = bhh[300 + GB]; bhn = bhh[600 + GB]; wm = mlpw[GB];
            xpb = xp + (size_t)seqv[sB] * LL * G3;
        }
        unsigned hl0 = 0, hl1 = 0;
        if (tid < 300) {
            hl0 = smem_u32(&s_h[0][sB][GB]);
            hl1 = smem_u32(&s_h[1][sB][GB]);
        }
        __syncthreads();
        CLUSTER_SYNC();

        int buf = 0;
        for (int t = 0; t < tmax; t++) {
            if (t > 0 && rank == 0 && tid < 4) {
                float* pp = s_partial + (buf ^ 1) * 16;
                float sum = pp[tid] + pp[4 + tid] + pp[8 + tid] + pp[12 + tid];
                if (t - 1 < lenv[tid]) attn[seqv[tid] * LL + (t - 1)] = fsig(sum + mbb) + 0.5f;
            }
            float gr = 0.f, gz = 0.f, gn2 = 0.f;
            if (tid < 300) {
                const float* xr = xpb + (size_t)t * G3;
                gr = xr[GB]; gz = xr[300 + GB]; gn2 = xr[600 + GB];
            }
            if (tid < 300) {
                __nv_bfloat16* hh = (__nv_bfloat16*)hb;
                #pragma unroll
                for (int s = 0; s < 4; s++)
                    hh[s * 312 + tid] = __float2bfloat16(s_h[buf][s][tid]);
            }
            __syncthreads();
            if (wid < 15) {
                float c0 = 0.f, c1 = 0.f, c2 = 0.f, c3 = 0.f;
                float d0 = 0.f, d1 = 0.f, d2 = 0.f, d3 = 0.f;
                #pragma unroll
                for (int kt = 0; kt < 19; kt += 2) {
                    unsigned b0 = hb[gid * 156 + kt * 8 + tig];
                    unsigned b1 = hb[gid * 156 + kt * 8 + tig + 4];
                    MMA16816(c0, c1, c2, c3, a[kt][0], a[kt][1], a[kt][2], a[kt][3], b0, b1);
                    if (kt + 1 < 19) {
                        unsigned e0 = hb[gid * 156 + (kt + 1) * 8 + tig];
                        unsigned e1 = hb[gid * 156 + (kt + 1) * 8 + tig + 4];
                        MMA16816(d0, d1, d2, d3, a[kt+1][0], a[kt+1][1], a[kt+1][2], a[kt+1][3], e0, e1);
                    }
                }
                c0 += d0; c1 += d1; c2 += d2; c3 += d3;
                if (tig < 2) {
                    int r0 = wid * 16 + gid;
                    *(float2*)&s_gate[r0][2 * tig]     = make_float2(c0, c1);
                    *(float2*)&s_gate[r0 + 8][2 * tig] = make_float2(c2, c3);
                }
            }
            __syncthreads();
            if (tid < 300) {
                float rp = s_gate[uB][sB];
                float zp = s_gate[75 + uB][sB];
                float np = s_gate[150 + uB][sB];
                float r = fsig(gr + rp + bhr);
                float z = fsig(gz + zp + bhz);
                float n = ftanh(gn2 + r * (np + bhn));
                h_reg = (1.f - z) * n + z * h_reg;
                unsigned la = buf ? hl0 : hl1;
                #pragma unroll
                for (unsigned rk = 0; rk < 4; rk++) dst_f32(la, rk, h_reg);
                s_red[sB * 80 + uB] = h_reg * wm;
            }
            __syncthreads();
            if (wid < 4) {
                float v = s_red[wid * 80 + lane];
                if (lane < 43) v += s_red[wid * 80 + lane + 32];
                if (lane < 11) v += s_red[wid * 80 + lane + 64];
                #pragma unroll
                for (int o = 16; o > 0; o >>= 1) v += __shfl_xor_sync(0xffffffffu, v, o);
                if (lane == 0) {
                    unsigned la = smem_u32(&s_partial[buf * 16 + (int)rank * 4 + wid]);
                    dst_f32(la, 0, v);
                }
            }
            CLUSTER_SYNC();
            buf ^= 1;
        }
        if (rank == 0 && tid < 4) {
            float* pp = s_partial + (buf ^ 1) * 16;
            float sum = pp[tid] + pp[4 + tid] + pp[8 + tid] + pp[12 + tid];
            if (tmax - 1 < lenv[tid]) attn[seqv[tid] * LL + (tmax - 1)] = fsig(sum + mbb) + 0.5f;
        }
        __syncthreads();
        CLUSTER_SYNC();
    }
}

// ---------------- K3: memory = emb[text] * scale ------------------------------
__global__ void k_mem(const int* __restrict__ text, const float* __restrict__ emb)
{
    int l = blockIdx.x, b = blockIdx.y, tid = threadIdx.x;
    if (tid >= EE) return;
    float* row = g_memory + ((size_t)b * LL + l) * EE;
    int ml = g_mem_len[b];
    if (l >= ml) { row[tid] = 0.f; return; }
    int astart = g_left_len[b] - g_asp_len[b];
    int aend = g_left_len[b];
    float al = g_attn_l[b * LL + l];
    int ridx = min(max(l - astart, 0), LL - 1);
    float arv = g_attn_r[b * LL + ridx];
    float sc = (l < astart) ? al : ((l < aend) ? (al + arv) : arv);
    int id = text[b * LL + l];
    row[tid] = emb[(size_t)id * EE + tid] * sc;
}

// ---------------- K4: v_s -----------------------------------------------------
__global__ void k_vs()
{
    int b = blockIdx.x, tid = threadIdx.x;
    if (tid >= EE) return;
    float acc = 0.f;
    const float* p = g_memory + (size_t)b * LL * EE + tid;
    int ml = g_mem_len[b];
    for (int l = 0; l < ml; l++) acc += p[(size_t)l * EE];
    g_vs[b * EE + tid] = acc / (float)ml;
}

// ---------------- K5: score->softmax->v_ts->proj->mlp->dense ------------------
__global__ void __launch_bounds__(512) k_tail(
    const float* __restrict__ attn_w, const float* __restrict__ b_k,
    const float* __restrict__ proj_w, const float* __restrict__ proj_b,
    const float* __restrict__ mlp_w, const float* __restrict__ mlp_b,
    const float* __restrict__ dense_w, const float* __restrict__ dense_b,
    float* __restrict__ out)
{
    int b = blockIdx.x, tid = threadIdx.x, lane = tid & 31, wid = tid >> 5;
    __shared__ float s_aw[EE];
    __shared__ float s_sc[LL];
    __shared__ float smax[16], ssum[16];
    __shared__ float s_v[EE], s_v2[EE];
    const float* kxb = g_kx + (size_t)b * LL * EE;
    int ml = g_mem_len[b];
    if (tid < EE) s_aw[tid] = attn_w[tid];
    __syncthreads();
    float qd = g_qdot[b];
    float sc_pad = tanhf(g_kpad + qd);
    for (int l = wid; l < ml; l += 16) {
        const float* row = kxb + (size_t)l * EE;
        float acc = 0.f;
        for (int e = lane; e < EE; e += 32) acc += row[e] * s_aw[e];
        #pragma unroll
        for (int o = 16; o > 0; o >>= 1) acc += __shfl_xor_sync(0xffffffffu, acc, o);
        if (lane == 0) s_sc[l] = tanhf(acc + qd);
    }
    __syncthreads();
    float x = (tid < ml) ? s_sc[tid] : sc_pad;
    float m = x;
    #pragma unroll
    for (int o = 16; o > 0; o >>= 1) m = fmaxf(m, __shfl_xor_sync(0xffffffffu, m, o));
    if (lane == 0) smax[wid] = m;
    __syncthreads();
    float bm = smax[0];
    #pragma unroll
    for (int w = 1; w < 16; w++) bm = fmaxf(bm, smax[w]);
    float p = expf(x - bm);
    float sm = p;
    #pragma unroll
    for (int o = 16; o > 0; o >>= 1) sm += __shfl_xor_sync(0xffffffffu, sm, o);
    if (lane == 0) ssum[wid] = sm;
    __syncthreads();
    float tot = 0.f;
    #pragma unroll
    for (int w = 0; w < 16; w++) tot += ssum[w];
    s_sc[tid] = p / tot;
    __syncthreads();
    float pad_prob = expf(sc_pad - bm) / tot;
    if (tid < EE) {
        float acc = (float)(LL - ml) * pad_prob * b_k[tid];
        for (int l = 0; l < ml; l++) acc += s_sc[l] * kxb[(size_t)l * EE + tid];
        s_v[tid] = acc;
    }
    __syncthreads();
    if (tid < EE) {
        float acc = proj_b[tid];
        const float* w = proj_w + (size_t)tid * EE;
        for (int e = 0; e < EE; e++) acc += s_v[e] * w[e];
        s_v2[tid] = acc + g_vs[b * EE + tid];
    }
    __syncthreads();
    if (tid < EE) {
        float acc = mlp_b[tid];
        const float* w = mlp_w + (size_t)tid * EE;
        for (int e = 0; e < EE; e++) acc += s_v2[e] * w[e];
        s_v[tid] = tanhf(acc);
    }
    __syncthreads();
    if (wid < 3) {
        const float* w = dense_w + (size_t)wid * EE;
        float acc = 0.f;
        for (int e = lane; e < EE; e += 32) acc += s_v[e] * w[e];
        #pragma unroll
        for (int o = 16; o > 0; o >>= 1) acc += __shfl_xor_sync(0xffffffffu, acc, o);
        if (lane == 0) out[b * 3 + wid] = acc + dense_b[wid];
    }
}

extern "C" void kernel_launch(void* const* d_in, const int* in_sizes, int n_in,
                              void* d_out, int out_size)
{
    const int*   text  = (const int*)d_in[0];
    const int*   aspi  = (const int*)d_in[1];
    const int*   xl    = (const int*)d_in[2];
    const int*   xr    = (const int*)d_in[3];
    const float* emb   = (const float*)d_in[4];
    const float* emb_a = (const float*)d_in[5];
    const float* Wih_l = (const float*)d_in[6];
    const float* Whh_l = (const float*)d_in[7];
    const float* bih_l = (const float*)d_in[8];
    const float* bhh_l = (const float*)d_in[9];
    const float* Wih_r = (const float*)d_in[10];
    const float* Whh_r = (const float*)d_in[11];
    const float* bih_r = (const float*)d_in[12];
    const float* bhh_r = (const float*)d_in[13];
    const float* mlw_l = (const float*)d_in[14];
    const float* mlb_l = (const float*)d_in[15];
    const float* mlw_r = (const float*)d_in[16];
    const float* mlb_r = (const float*)d_in[17];
    const float* w_k   = (const float*)d_in[18];
    const float* b_k   = (const float*)d_in[19];
    const float* w_q   = (const float*)d_in[20];
    const float* b_q   = (const float*)d_in[21];
    const float* aw    = (const float*)d_in[22];
    const float* pw    = (const float*)d_in[23];
    const float* pb    = (const float*)d_in[24];
    const float* mw    = (const float*)d_in[25];
    const float* mb    = (const float*)d_in[26];
    const float* dw    = (const float*)d_in[27];
    const float* db    = (const float*)d_in[28];
    float* out = (float*)d_out;

    const int GEMM_SMEM = 2 * 64 * 312 * 2;   // 79872 B -> 2 CTA/SM
    cudaFuncSetAttribute(k_gemm3, cudaFuncAttributeMaxDynamicSharedMemorySize, GEMM_SMEM);

    k_wpk2<<<dim3(285, 8), 128>>>(Whh_l, Whh_r);
    k_init<<<BB, 512>>>(text, aspi, xl, xr, emb_a, w_q, b_q, aw, mlb_l, mlb_r);
    k_sched<<<1, 256>>>(b_k, aw);

    dim3 gx((G3 + 63) / 64, LL / 64, BB);
    k_gemm3<<<gx, 256, GEMM_SMEM>>>(emb, xl, Wih_l, bih_l, G3, 0, 1);
    k_gemm3<<<gx, 256, GEMM_SMEM>>>(emb, xr, Wih_r, bih_r, G3, 1, 2);

    k_gruT<<<BB, 512>>>(bhh_l, bhh_r, mlw_l, mlb_l, mlw_r, mlb_r);

    k_mem<<<dim3(LL, BB), 320>>>(text, emb);
    k_vs<<<BB, 320>>>();

    dim3 gk((EE + 63) / 64, LL / 64, BB);
    k_gemm3<<<gk, 256, GEMM_SMEM>>>(emb, (const int*)0, w_k, b_k, EE, 2, 3);

    k_tail<<<BB, 512>>>(aw, b_k, pw, pb, mw, mb, dw, db, out);
}

// round 14
// speedup vs baseline: 1.8706x; 1.2021x over previous
#include <cuda_runtime.h>
#include <cuda_bf16.h>
#include <cuda_fp16.h>
#include <math.h>

#define BB 128
#define LL 512
#define LAa 8
#define EE 300
#define HH 300
#define G3 900

__device__ __align__(16) int   g_mem_len[BB];
__device__ __align__(16) int   g_asp_len[BB];
__device__ __align__(16) int   g_left_len[BB];
__device__ __align__(16) int   g_right_len[BB];
__device__ __align__(16) float g_qdot[BB];
__device__ __align__(16) float g_attn_l[BB * LL];
__device__ __align__(16) float g_attn_r[BB * LL];
__device__ __align__(16) float g_xp_l[(size_t)BB * LL * G3];
__device__ __align__(16) float g_xp_r[(size_t)BB * LL * G3];
__device__ __align__(16) float g_kx[(size_t)BB * LL * EE];
__device__ __align__(16) float g_vs[BB * EE];

// cluster-GRU schedule
__device__ int   g_grp_seq[64][4];
__device__ int   g_grp_len[64][4];
__device__ int   g_grp_maxlen[64];
__device__ int   g_grp_side[64];
__device__ int   g_clu_grp[32][2];
__device__ float g_kpad;
// mma A-fragment-packed weights: [(side*4+rank)*15+w][kt][lane][4] b32 (bf16x2)
// row 225 carries mlp_w (attn dot folded into MMA)
__device__ __align__(16) unsigned g_Wmma[8 * 15 * 19 * 128];

__device__ __forceinline__ float sigf(float x) { return 1.0f / (1.0f + expf(-x)); }
__device__ __forceinline__ float ftanh(float x) {
    float y; asm("tanh.approx.f32 %0, %1;" : "=f"(y) : "f"(x)); return y;
}
__device__ __forceinline__ float fsig(float x) { return 0.5f * ftanh(0.5f * x) + 0.5f; }

__device__ __forceinline__ unsigned smem_u32(const void* p) {
    unsigned r;
    asm("{ .reg .u64 t; cvta.to.shared.u64 t, %1; cvt.u32.u64 %0, t; }" : "=r"(r) : "l"(p));
    return r;
}
__device__ __forceinline__ unsigned ctarank() {
    unsigned r; asm("mov.u32 %0, %%cluster_ctarank;" : "=r"(r)); return r;
}
#define CLUSTER_SYNC() do { \
    asm volatile("barrier.cluster.arrive.aligned;" ::: "memory"); \
    asm volatile("barrier.cluster.wait.aligned;" ::: "memory"); } while (0)

__device__ __forceinline__ void dst_f32(unsigned laddr, unsigned rk, float v) {
    asm volatile("{ .reg .b32 ra; mapa.shared::cluster.u32 ra, %0, %1; "
                 "st.shared::cluster.b32 [ra], %2; }"
                 :: "r"(laddr), "r"(rk), "r"(__float_as_uint(v)) : "memory");
}

#define MMA16816(c0,c1,c2,c3,a0,a1,a2,a3,b0,b1) \
    asm volatile("mma.sync.aligned.m16n8k16.row.col.f32.bf16.bf16.f32 " \
                 "{%0,%1,%2,%3}, {%4,%5,%6,%7}, {%8,%9}, {%0,%1,%2,%3};" \
                 : "+f"(c0), "+f"(c1), "+f"(c2), "+f"(c3) \
                 : "r"(a0), "r"(a1), "r"(a2), "r"(a3), "r"(b0), "r"(b1))

#define MMAH16816(c0,c1,c2,c3,a0,a1,a2,a3,b0,b1) \
    asm volatile("mma.sync.aligned.m16n8k16.row.col.f32.f16.f16.f32 " \
                 "{%0,%1,%2,%3}, {%4,%5,%6,%7}, {%8,%9}, {%0,%1,%2,%3};" \
                 : "+f"(c0), "+f"(c1), "+f"(c2), "+f"(c3) \
                 : "r"(a0), "r"(a1), "r"(a2), "r"(a3), "r"(b0), "r"(b1))

// ---------------- K_wpk2: pack W_hh (+mlp_w row 225) into mma A-frag layout ---
__global__ void k_wpk2(const float* __restrict__ Whh_l, const float* __restrict__ Whh_r,
                       const float* __restrict__ mlpw_l, const float* __restrict__ mlpw_r)
{
    int tid = threadIdx.x;                 // 128
    int j = tid >> 5, l = tid & 31;
    int gid = l >> 2, tig = l & 3;
    int wkt = blockIdx.x;                  // 0..284
    int w = wkt / 19, kt = wkt % 19;
    int sr = blockIdx.y;                   // 0..7
    int side = sr >> 2, rank = sr & 3;
    const float* W = side ? Whh_r : Whh_l;
    const float* M = side ? mlpw_r : mlpw_l;

    int rl = gid + ((j & 1) ? 8 : 0);
    int k  = kt * 16 + tig * 2 + ((j >= 2) ? 8 : 0);
    int r  = 16 * w + rl;
    float lo = 0.f, hi = 0.f;
    if (r < 225) {
        int G = (r / 75) * 300 + rank * 75 + (r % 75);
        if (k < 300)     lo = W[(size_t)G * HH + k];
        if (k + 1 < 300) hi = W[(size_t)G * HH + k + 1];
    } else if (r == 225) {
        if (k < 300)     lo = M[k];
        if (k + 1 < 300) hi = M[k + 1];
    }
    __nv_bfloat162 p = __floats2bfloat162_rn(lo, hi);
    g_Wmma[(size_t)((sr * 15 + w) * 19 + kt) * 128 + l * 4 + j] = *(unsigned*)&p;
}

// ---------------- K0: lengths, attn defaults, aspect mean -> qdot -------------
__global__ void k_init(const int* __restrict__ text, const int* __restrict__ aspi,
                       const int* __restrict__ xl, const int* __restrict__ xr,
                       const float* __restrict__ emb_aspect,
                       const float* __restrict__ w_q, const float* __restrict__ b_q,
                       const float* __restrict__ attn_w,
                       const float* __restrict__ mlp_l_b, const float* __restrict__ mlp_r_b)
{
    int b = blockIdx.x, tid = threadIdx.x;
    int ml = __syncthreads_count(text[b * LL + tid] != 0);
    int ll = __syncthreads_count(xl[b * LL + tid] != 0);
    int rl = __syncthreads_count(xr[b * LL + tid] != 0);
    int al = __syncthreads_count((tid < LAa) && (aspi[b * LAa + tid] != 0));
    if (tid == 0) { g_mem_len[b] = ml; g_left_len[b] = ll; g_right_len[b] = rl; g_asp_len[b] = al; }
    g_attn_l[b * LL + tid] = sigf(mlp_l_b[0]) + 0.5f;
    g_attn_r[b * LL + tid] = sigf(mlp_r_b[0]) + 0.5f;

    __shared__ float s_asp[EE];
    __shared__ float sred[16];
    if (tid < EE) {
        float acc = 0.f;
        #pragma unroll
        for (int a = 0; a < LAa; a++)
            if (a < al) acc += emb_aspect[(size_t)aspi[b * LAa + a] * EE + tid];
        s_asp[tid] = acc / (float)al;
    }
    __syncthreads();
    float val = 0.f;
    if (tid < EE) {
        float acc = b_q[tid];
        const float* wq = w_q + (size_t)tid * EE;
        for (int e = 0; e < EE; e++) acc += s_asp[e] * wq[e];
        val = acc * attn_w[EE + tid];
    }
    #pragma unroll
    for (int o = 16; o > 0; o >>= 1) val += __shfl_xor_sync(0xffffffffu, val, o);
    if ((tid & 31) == 0) sred[tid >> 5] = val;
    __syncthreads();
    if (tid == 0) {
        float s = 0.f;
        #pragma unroll
        for (int w = 0; w < 16; w++) s += sred[w];
        g_qdot[b] = s;
    }
}

// ---------------- K_sched: groups of 4 per side, snake over 32 clusters -------
__global__ void k_sched(const float* __restrict__ b_k, const float* __restrict__ attn_w)
{
    __shared__ float sred[256];
    int i = threadIdx.x;  // 256 threads, 1 block
    float p = 0.f;
    for (int e = i; e < EE; e += 256) p += b_k[e] * attn_w[e];
    sred[i] = p;
    __syncthreads();
    if (i == 0) { float s = 0.f; for (int m = 0; m < 256; m++) s += sred[m]; g_kpad = s; }

    int side = i >> 7, j = i & 127;
    const int* lens = side ? g_right_len : g_left_len;
    int lj = lens[j], r = 0;
    for (int m = 0; m < BB; m++) {
        int lm = lens[m];
        r += (lm > lj) || (lm == lj && m < j);
    }
    int g = side * 32 + (r >> 2);
    g_grp_seq[g][r & 3] = j;
    g_grp_len[g][r & 3] = lj;
    if ((r & 3) == 0) { g_grp_maxlen[g] = lj; g_grp_side[g] = side; }
    __syncthreads();
    if (i < 64) {
        int ml = g_grp_maxlen[i]; int r2 = 0;
        for (int m = 0; m < 64; m++) {
            int lm = g_grp_maxlen[m];
            r2 += (lm > ml) || (lm == ml && m < i);
        }
        int cl = (r2 < 32) ? r2 : 63 - r2;
        g_clu_grp[cl][(r2 < 32) ? 0 : 1] = i;
    }
}

// ---------------- K1: GEMM v7 — fp16 HMMA, structured staging, inline scale ---
// A row = emb[ids[b][m]] (optionally * memory-scale when limit_sel==3)
__global__ void __launch_bounds__(256, 2) k_gemm3(
    const float* __restrict__ emb, const int* __restrict__ ids,
    const float* __restrict__ W, const float* __restrict__ bias,
    int N, int dst_sel, int limit_sel)
{
    int b = blockIdx.z, m0 = blockIdx.y * 64, n0 = blockIdx.x * 64;
    int lim = (limit_sel == 1) ? g_left_len[b] : (limit_sel == 2) ? g_right_len[b]
            : g_mem_len[b];
    if (m0 >= lim) return;

    float* C = (dst_sel == 0) ? g_xp_l : (dst_sel == 1) ? g_xp_r : g_kx;
    float* Cb = C + (size_t)b * LL * N;
    const int* bids = ids + (size_t)b * LL;

    extern __shared__ __align__(16) __half smem[];
    __half* As = smem;              // [64][312]
    __half* Bs = smem + 64 * 312;   // [64][312]

    int tid = threadIdx.x, lane = tid & 31, wid = tid >> 5;
    int gid = lane >> 2, tig = lane & 3;
    int row = tid >> 2, tpr = tid & 3;

    // zero k-pad region (b32 words 150..155 of each row)
    for (int idx = tid; idx < 64 * 6; idx += 256) {
        int rr = idx / 6, w = idx % 6;
        ((unsigned*)(As + rr * 312))[150 + w] = 0u;
        ((unsigned*)(Bs + rr * 312))[150 + w] = 0u;
    }
    // ---- stage A: one row per 4 threads, pointer + scale computed once ----
    {
        int gm = m0 + row;
        float sc = 1.f;
        if (limit_sel == 3) {
            int ml = g_mem_len[b];
            if (gm < ml) {
                int astart = g_left_len[b] - g_asp_len[b];
                int aend = g_left_len[b];
                float al = g_attn_l[b * LL + gm];
                int ridx = min(max(gm - astart, 0), LL - 1);
                float arv = g_attn_r[b * LL + ridx];
                sc = (gm < astart) ? al : ((gm < aend) ? (al + arv) : arv);
            } else sc = 0.f;
        }
        const float* ar = emb + (size_t)bids[gm] * EE;
        unsigned* dstrow = (unsigned*)(As + row * 312);
        #pragma unroll
        for (int k = 0; k < 19; k++) {
            int c4 = tpr + 4 * k;
            if (c4 < 75) {
                float4 v = *(const float4*)(ar + c4 * 4);
                __half2 p0 = __floats2half2_rn(v.x * sc, v.y * sc);
                __half2 p1 = __floats2half2_rn(v.z * sc, v.w * sc);
                dstrow[c4 * 2]     = *(unsigned*)&p0;
                dstrow[c4 * 2 + 1] = *(unsigned*)&p1;
            }
        }
    }
    // ---- stage B ----
    {
        int gn = n0 + row;
        const float* br = (gn < N) ? (W + (size_t)gn * EE) : (const float*)0;
        unsigned* dstrow = (unsigned*)(Bs + row * 312);
        #pragma unroll
        for (int k = 0; k < 19; k++) {
            int c4 = tpr + 4 * k;
            if (c4 < 75) {
                if (br) {
                    float4 v = *(const float4*)(br + c4 * 4);
                    __half2 p0 = __floats2half2_rn(v.x, v.y);
                    __half2 p1 = __floats2half2_rn(v.z, v.w);
                    dstrow[c4 * 2]     = *(unsigned*)&p0;
                    dstrow[c4 * 2 + 1] = *(unsigned*)&p1;
                } else {
                    dstrow[c4 * 2] = 0u; dstrow[c4 * 2 + 1] = 0u;
                }
            }
        }
    }
    __syncthreads();

    int wm = wid >> 1, wn = wid & 1;
    const unsigned* A32 = (const unsigned*)As;   // row stride 156 words
    const unsigned* B32 = (const unsigned*)Bs;
    float c[4][4];
    #pragma unroll
    for (int t = 0; t < 4; t++)
        #pragma unroll
        for (int r = 0; r < 4; r++) c[t][r] = 0.f;

    int arow0 = (wm * 16 + gid) * 156;
    int arow1 = arow0 + 8 * 156;
    #pragma unroll
    for (int kt = 0; kt < 19; kt++) {
        int ka = kt * 8 + tig;
        unsigned a0 = A32[arow0 + ka];
        unsigned a1 = A32[arow1 + ka];
        unsigned a2 = A32[arow0 + ka + 4];
        unsigned a3 = A32[arow1 + ka + 4];
        #pragma unroll
        for (int t = 0; t < 4; t++) {
            int nr = (wn * 32 + t * 8 + gid) * 156;
            unsigned b0 = B32[nr + ka];
            unsigned b1 = B32[nr + ka + 4];
            MMAH16816(c[t][0], c[t][1], c[t][2], c[t][3], a0, a1, a2, a3, b0, b1);
        }
    }
    #pragma unroll
    for (int t = 0; t < 4; t++) {
        int on = n0 + wn * 32 + t * 8 + tig * 2;
        int om = m0 + wm * 16 + gid;
        if (on < N) {
            float bi = bias[on];
            Cb[(size_t)om * N + on]       = c[t][0] + bi;
            Cb[(size_t)(om + 8) * N + on] = c[t][2] + bi;
        }
        if (on + 1 < N) {
            float bi = bias[on + 1];
            Cb[(size_t)om * N + on + 1]       = c[t][1] + bi;
            Cb[(size_t)(om + 8) * N + on + 1] = c[t][3] + bi;
        }
    }
}

// ---------------- K2: cluster-4 GRU, HMMA GEMV with folded attn row -----------
__global__ void __launch_bounds__(512, 1) __cluster_dims__(4, 1, 1)
k_gruT(const float* __restrict__ bhh_l, const float* __restrict__ bhh_r,
       const float* __restrict__ mlpb_l, const float* __restrict__ mlpb_r)
{
    __shared__ __align__(16) float s_h[2][4][304];
    __shared__ __align__(16) unsigned hb[8 * 156];
    __shared__ __align__(16) float s_gate[240][4];

    int tid = threadIdx.x, lane = tid & 31, wid = tid >> 5;
    int gid = lane >> 2, tig = lane & 3;
    unsigned rank = ctarank();
    int c = blockIdx.x >> 2;

    for (int gi = 0; gi < 2; gi++) {
        int grp  = g_clu_grp[c][gi];
        int side = g_grp_side[grp];
        int tmax = g_grp_maxlen[grp];
        const float* bhh  = side ? bhh_r : bhh_l;
        float mbb = side ? mlpb_r[0] : mlpb_l[0];
        const float* xp = side ? g_xp_r : g_xp_l;
        float* attn = side ? g_attn_r : g_attn_l;
        int seqv[4], lenv[4];
        #pragma unroll
        for (int s = 0; s < 4; s++) { seqv[s] = g_grp_seq[grp][s]; lenv[s] = g_grp_len[grp][s]; }

        for (int i = tid; i < 2 * 4 * 304; i += 512) ((float*)s_h)[i] = 0.f;
        for (int i = tid; i < 8 * 156; i += 512) hb[i] = 0u;

        unsigned a[19][4];
        if (wid < 15) {
            const uint4* src = (const uint4*)g_Wmma
                             + (size_t)(((side * 4 + (int)rank) * 15 + wid) * 19) * 32 + lane;
            #pragma unroll
            for (int kt = 0; kt < 19; kt++) {
                uint4 v = src[kt * 32];
                a[kt][0] = v.x; a[kt][1] = v.y; a[kt][2] = v.z; a[kt][3] = v.w;
            }
        }

        int sB = tid / 75, uB = tid % 75, GB = (int)rank * 75 + uB;
        float bhr = 0.f, bhz = 0.f, bhn = 0.f, h_reg = 0.f;
        const float* xpb = 0;
        if (tid < 300) {
            bhr = bhh[GB]; bhz = bhh[300 + GB]; bhn = bhh[600 + GB];
            xpb = xp + (size_t)seqv[sB] * LL * G3;
        }
        unsigned hl0 = 0, hl1 = 0;
        if (tid < 300) {
            hl0 = smem_u32(&s_h[0][sB][GB]);
            hl1 = smem_u32(&s_h[1][sB][GB]);
        }
        __syncthreads();
        CLUSTER_SYNC();

        int buf = 0;
        for (int t = 0; t < tmax; t++) {
            float gr = 0.f, gz = 0.f, gn2 = 0.f;
            if (tid < 300) {
                const float* xr = xpb + (size_t)t * G3;
                gr = xr[GB]; gz = xr[300 + GB]; gn2 = xr[600 + GB];
            }
            // stage1: fp32 h -> bf16 B-layout
            if (tid < 300) {
                __nv_bfloat16* hh = (__nv_bfloat16*)hb;
                #pragma unroll
                for (int s = 0; s < 4; s++)
                    hh[s * 312 + tid] = __float2bfloat16(s_h[buf][s][tid]);
            }
            __syncthreads();
            // stage2: tensor GEMV (rows 0..224 gates; row 225 = wm.h_{t-1})
            if (wid < 15) {
                float c0 = 0.f, c1 = 0.f, c2 = 0.f, c3 = 0.f;
                float d0 = 0.f, d1 = 0.f, d2 = 0.f, d3 = 0.f;
                #pragma unroll
                for (int kt = 0; kt < 19; kt += 2) {
                    unsigned b0 = hb[gid * 156 + kt * 8 + tig];
                    unsigned b1 = hb[gid * 156 + kt * 8 + tig + 4];
                    MMA16816(c0, c1, c2, c3, a[kt][0], a[kt][1], a[kt][2], a[kt][3], b0, b1);
                    if (kt + 1 < 19) {
                        unsigned e0 = hb[gid * 156 + (kt + 1) * 8 + tig];
                        unsigned e1 = hb[gid * 156 + (kt + 1) * 8 + tig + 4];
                        MMA16816(d0, d1, d2, d3, a[kt+1][0], a[kt+1][1], a[kt+1][2], a[kt+1][3], e0, e1);
                    }
                }
                c0 += d0; c1 += d1; c2 += d2; c3 += d3;
                if (tig < 2) {
                    int r0 = wid * 16 + gid;
                    *(float2*)&s_gate[r0][2 * tig]     = make_float2(c0, c1);
                    *(float2*)&s_gate[r0 + 8][2 * tig] = make_float2(c2, c3);
                }
            }
            __syncthreads();
            // stage3: gate math + h broadcast; rank0 emits attn[t-1]
            if (tid < 300) {
                float rp = s_gate[uB][sB];
                float zp = s_gate[75 + uB][sB];
                float np = s_gate[150 + uB][sB];
                float r = fsig(gr + rp + bhr);
                float z = fsig(gz + zp + bhz);
                float n = ftanh(gn2 + r * (np + bhn));
                h_reg = (1.f - z) * n + z * h_reg;
                unsigned la = buf ? hl0 : hl1;
                #pragma unroll
                for (unsigned rk = 0; rk < 4; rk++) dst_f32(la, rk, h_reg);
            }
            if (t > 0 && rank == 0 && tid >= 300 && tid < 304) {
                int s = tid - 300;
                if (t - 1 < lenv[s])
                    attn[seqv[s] * LL + (t - 1)] = fsig(s_gate[225][s] + mbb) + 0.5f;
            }
            CLUSTER_SYNC();
            buf ^= 1;
        }
        // final attn for t = tmax-1 (one extra row-225 MMA on h_{tmax-1})
        if (tid < 300) {
            __nv_bfloat16* hh = (__nv_bfloat16*)hb;
            #pragma unroll
            for (int s = 0; s < 4; s++)
                hh[s * 312 + tid] = __float2bfloat16(s_h[buf][s][tid]);
        }
        __syncthreads();
        if (wid == 14) {
            float c0 = 0.f, c1 = 0.f, c2 = 0.f, c3 = 0.f;
            #pragma unroll
            for (int kt = 0; kt < 19; kt++) {
                unsigned b0 = hb[gid * 156 + kt * 8 + tig];
                unsigned b1 = hb[gid * 156 + kt * 8 + tig + 4];
                MMA16816(c0, c1, c2, c3, a[kt][0], a[kt][1], a[kt][2], a[kt][3], b0, b1);
            }
            if (tig < 2) {
                int r0 = 14 * 16 + gid;
                *(float2*)&s_gate[r0][2 * tig]     = make_float2(c0, c1);
                *(float2*)&s_gate[r0 + 8][2 * tig] = make_float2(c2, c3);
            }
        }
        __syncthreads();
        if (rank == 0 && tid < 4) {
            if (tmax - 1 < lenv[tid])
                attn[seqv[tid] * LL + (tmax - 1)] = fsig(s_gate[225][tid] + mbb) + 0.5f;
        }
        __syncthreads();
        CLUSTER_SYNC();
    }
}

// ---------------- K4: v_s (gathers emb directly; no g_memory) -----------------
__global__ void k_vs(const int* __restrict__ text, const float* __restrict__ emb)
{
    int b = blockIdx.x, tid = threadIdx.x;
    if (tid >= EE) return;
    int ml = g_mem_len[b];
    int astart = g_left_len[b] - g_asp_len[b];
    int aend = g_left_len[b];
    float acc = 0.f;
    for (int l = 0; l < ml; l++) {
        float al = g_attn_l[b * LL + l];
        int ridx = min(max(l - astart, 0), LL - 1);
        float arv = g_attn_r[b * LL + ridx];
        float sc = (l < astart) ? al : ((l < aend) ? (al + arv) : arv);
        int id = text[b * LL + l];
        acc += emb[(size_t)id * EE + tid] * sc;
    }
    g_vs[b * EE + tid] = acc / (float)ml;
}

// ---------------- K5: score->softmax->v_ts->proj->mlp->dense ------------------
__global__ void __launch_bounds__(512) k_tail(
    const float* __restrict__ attn_w, const float* __restrict__ b_k,
    const float* __restrict__ proj_w, const float* __restrict__ proj_b,
    const float* __restrict__ mlp_w, const float* __restrict__ mlp_b,
    const float* __restrict__ dense_w, const float* __restrict__ dense_b,
    float* __restrict__ out)
{
    int b = blockIdx.x, tid = threadIdx.x, lane = tid & 31, wid = tid >> 5;
    __shared__ float s_aw[EE];
    __shared__ float s_sc[LL];
    __shared__ float smax[16], ssum[16];
    __shared__ float s_v[EE], s_v2[EE];
    const float* kxb = g_kx + (size_t)b * LL * EE;
    int ml = g_mem_len[b];
    if (tid < EE) s_aw[tid] = attn_w[tid];
    __syncthreads();
    float qd = g_qdot[b];
    float sc_pad = tanhf(g_kpad + qd);
    for (int l = wid; l < ml; l += 16) {
        const float* row = kxb + (size_t)l * EE;
        float acc = 0.f;
        for (int e = lane; e < EE; e += 32) acc += row[e] * s_aw[e];
        #pragma unroll
        for (int o = 16; o > 0; o >>= 1) acc += __shfl_xor_sync(0xffffffffu, acc, o);
        if (lane == 0) s_sc[l] = tanhf(acc + qd);
    }
    __syncthreads();
    float x = (tid < ml) ? s_sc[tid] : sc_pad;
    float m = x;
    #pragma unroll
    for (int o = 16; o > 0; o >>= 1) m = fmaxf(m, __shfl_xor_sync(0xffffffffu, m, o));
    if (lane == 0) smax[wid] = m;
    __syncthreads();
    float bm = smax[0];
    #pragma unroll
    for (int w = 1; w < 16; w++) bm = fmaxf(bm, smax[w]);
    float p = expf(x - bm);
    float sm = p;
    #pragma unroll
    for (int o = 16; o > 0; o >>= 1) sm += __shfl_xor_sync(0xffffffffu, sm, o);
    if (lane == 0) ssum[wid] = sm;
    __syncthreads();
    float tot = 0.f;
    #pragma unroll
    for (int w = 0; w < 16; w++) tot += ssum[w];
    s_sc[tid] = p / tot;
    __syncthreads();
    float pad_prob = expf(sc_pad - bm) / tot;
    if (tid < EE) {
        float acc = (float)(LL - ml) * pad_prob * b_k[tid];
        for (int l = 0; l < ml; l++) acc += s_sc[l] * kxb[(size_t)l * EE + tid];
        s_v[tid] = acc;
    }
    __syncthreads();
    if (tid < EE) {
        float acc = proj_b[tid];
        const float* w = proj_w + (size_t)tid * EE;
        for (int e = 0; e < EE; e++) acc += s_v[e] * w[e];
        s_v2[tid] = acc + g_vs[b * EE + tid];
    }
    __syncthreads();
    if (tid < EE) {
        float acc = mlp_b[tid];
        const float* w = mlp_w + (size_t)tid * EE;
        for (int e = 0; e < EE; e++) acc += s_v2[e] * w[e];
        s_v[tid] = tanhf(acc);
    }
    __syncthreads();
    if (wid < 3) {
        const float* w = dense_w + (size_t)wid * EE;
        float acc = 0.f;
        for (int e = lane; e < EE; e += 32) acc += s_v[e] * w[e];
        #pragma unroll
        for (int o = 16; o > 0; o >>= 1) acc += __shfl_xor_sync(0xffffffffu, acc, o);
        if (lane == 0) out[b * 3 + wid] = acc + dense_b[wid];
    }
}

extern "C" void kernel_launch(void* const* d_in, const int* in_sizes, int n_in,
                              void* d_out, int out_size)
{
    const int*   text  = (const int*)d_in[0];
    const int*   aspi  = (const int*)d_in[1];
    const int*   xl    = (const int*)d_in[2];
    const int*   xr    = (const int*)d_in[3];
    const float* emb   = (const float*)d_in[4];
    const float* emb_a = (const float*)d_in[5];
    const float* Wih_l = (const float*)d_in[6];
    const float* Whh_l = (const float*)d_in[7];
    const float* bih_l = (const float*)d_in[8];
    const float* bhh_l = (const float*)d_in[9];
    const float* Wih_r = (const float*)d_in[10];
    const float* Whh_r = (const float*)d_in[11];
    const float* bih_r = (const float*)d_in[12];
    const float* bhh_r = (const float*)d_in[13];
    const float* mlw_l = (const float*)d_in[14];
    const float* mlb_l = (const float*)d_in[15];
    const float* mlw_r = (const float*)d_in[16];
    const float* mlb_r = (const float*)d_in[17];
    const float* w_k   = (const float*)d_in[18];
    const float* b_k   = (const float*)d_in[19];
    const float* w_q   = (const float*)d_in[20];
    const float* b_q   = (const float*)d_in[21];
    const float* aw    = (const float*)d_in[22];
    const float* pw    = (const float*)d_in[23];
    const float* pb    = (const float*)d_in[24];
    const float* mw    = (const float*)d_in[25];
    const float* mb    = (const float*)d_in[26];
    const float* dw    = (const float*)d_in[27];
    const float* db    = (const float*)d_in[28];
    float* out = (float*)d_out;

    const int GEMM_SMEM = 2 * 64 * 312 * 2;   // 79872 B -> 2 CTA/SM
    cudaFuncSetAttribute(k_gemm3, cudaFuncAttributeMaxDynamicSharedMemorySize, GEMM_SMEM);

    k_wpk2<<<dim3(285, 8), 128>>>(Whh_l, Whh_r, mlw_l, mlw_r);
    k_init<<<BB, 512>>>(text, aspi, xl, xr, emb_a, w_q, b_q, aw, mlb_l, mlb_r);
    k_sched<<<1, 256>>>(b_k, aw);

    dim3 gx((G3 + 63) / 64, LL / 64, BB);
    k_gemm3<<<gx, 256, GEMM_SMEM>>>(emb, xl, Wih_l, bih_l, G3, 0, 1);
    k_gemm3<<<gx, 256, GEMM_SMEM>>>(emb, xr, Wih_r, bih_r, G3, 1, 2);

    k_gruT<<<BB, 512>>>(bhh_l, bhh_r, mlb_l, mlb_r);

    k_vs<<<BB, 320>>>(text, emb);

    dim3 gk((EE + 63) / 64, LL / 64, BB);
    k_gemm3<<<gk, 256, GEMM_SMEM>>>(emb, text, w_k, b_k, EE, 2, 3);

    k_tail<<<BB, 512>>>(aw, b_k, pw, pb, mw, mb, dw, db, out);
}

// round 15
// speedup vs baseline: 2.2430x; 1.1991x over previous
#include <cuda_runtime.h>
#include <cuda_bf16.h>
#include <cuda_fp16.h>
#include <math.h>

#define BB 128
#define LL 512
#define LAa 8
#define EE 300
#define HH 300
#define G3 900

__device__ __align__(16) int   g_mem_len[BB];
__device__ __align__(16) int   g_asp_len[BB];
__device__ __align__(16) int   g_left_len[BB];
__device__ __align__(16) int   g_right_len[BB];
__device__ __align__(16) float g_qdot[BB];
__device__ __align__(16) float g_attn_l[BB * LL];
__device__ __align__(16) float g_attn_r[BB * LL];
__device__ __align__(16) float g_xp_l[(size_t)BB * LL * G3];
__device__ __align__(16) float g_xp_r[(size_t)BB * LL * G3];
__device__ __align__(16) float g_kx[(size_t)BB * LL * EE];
__device__ __align__(16) float g_vs[BB * EE];

// cluster-GRU schedule
__device__ int   g_grp_seq[64][4];
__device__ int   g_grp_len[64][4];
__device__ int   g_grp_maxlen[64];
__device__ int   g_grp_side[64];
__device__ int   g_clu_grp[32][2];
__device__ float g_kpad;
// mma A-fragment-packed weights: [(side*4+rank)*15+w][kt][lane][4] b32 (bf16x2)
// row 225 carries mlp_w (attn dot folded into MMA)
__device__ __align__(16) unsigned g_Wmma[8 * 15 * 19 * 128];

__device__ __forceinline__ float sigf(float x) { return 1.0f / (1.0f + expf(-x)); }
__device__ __forceinline__ float ftanh(float x) {
    float y; asm("tanh.approx.f32 %0, %1;" : "=f"(y) : "f"(x)); return y;
}
__device__ __forceinline__ float fsig(float x) { return 0.5f * ftanh(0.5f * x) + 0.5f; }

__device__ __forceinline__ unsigned smem_u32(const void* p) {
    unsigned r;
    asm("{ .reg .u64 t; cvta.to.shared.u64 t, %1; cvt.u32.u64 %0, t; }" : "=r"(r) : "l"(p));
    return r;
}
__device__ __forceinline__ unsigned ctarank() {
    unsigned r; asm("mov.u32 %0, %%cluster_ctarank;" : "=r"(r)); return r;
}
#define CLUSTER_SYNC() do { \
    asm volatile("barrier.cluster.arrive.aligned;" ::: "memory"); \
    asm volatile("barrier.cluster.wait.aligned;" ::: "memory"); } while (0)
#define CLU_ARRIVE() asm volatile("barrier.cluster.arrive.aligned;" ::: "memory")
#define CLU_WAIT()   asm volatile("barrier.cluster.wait.aligned;" ::: "memory")

__device__ __forceinline__ void dst_b16(unsigned laddr, unsigned rk, unsigned short v) {
    asm volatile("{ .reg .b32 ra; mapa.shared::cluster.u32 ra, %0, %1; "
                 "st.shared::cluster.b16 [ra], %2; }"
                 :: "r"(laddr), "r"(rk), "h"(v) : "memory");
}

#define MMA16816(c0,c1,c2,c3,a0,a1,a2,a3,b0,b1) \
    asm volatile("mma.sync.aligned.m16n8k16.row.col.f32.bf16.bf16.f32 " \
                 "{%0,%1,%2,%3}, {%4,%5,%6,%7}, {%8,%9}, {%0,%1,%2,%3};" \
                 : "+f"(c0), "+f"(c1), "+f"(c2), "+f"(c3) \
                 : "r"(a0), "r"(a1), "r"(a2), "r"(a3), "r"(b0), "r"(b1))

#define MMAH16816(c0,c1,c2,c3,a0,a1,a2,a3,b0,b1) \
    asm volatile("mma.sync.aligned.m16n8k16.row.col.f32.f16.f16.f32 " \
                 "{%0,%1,%2,%3}, {%4,%5,%6,%7}, {%8,%9}, {%0,%1,%2,%3};" \
                 : "+f"(c0), "+f"(c1), "+f"(c2), "+f"(c3) \
                 : "r"(a0), "r"(a1), "r"(a2), "r"(a3), "r"(b0), "r"(b1))

// ---------------- K_wpk2: pack W_hh (+mlp_w row 225) into mma A-frag layout ---
__global__ void k_wpk2(const float* __restrict__ Whh_l, const float* __restrict__ Whh_r,
                       const float* __restrict__ mlpw_l, const float* __restrict__ mlpw_r)
{
    int tid = threadIdx.x;                 // 128
    int j = tid >> 5, l = tid & 31;
    int gid = l >> 2, tig = l & 3;
    int wkt = blockIdx.x;                  // 0..284
    int w = wkt / 19, kt = wkt % 19;
    int sr = blockIdx.y;                   // 0..7
    int side = sr >> 2, rank = sr & 3;
    const float* W = side ? Whh_r : Whh_l;
    const float* M = side ? mlpw_r : mlpw_l;

    int rl = gid + ((j & 1) ? 8 : 0);
    int k  = kt * 16 + tig * 2 + ((j >= 2) ? 8 : 0);
    int r  = 16 * w + rl;
    float lo = 0.f, hi = 0.f;
    if (r < 225) {
        int G = (r / 75) * 300 + rank * 75 + (r % 75);
        if (k < 300)     lo = W[(size_t)G * HH + k];
        if (k + 1 < 300) hi = W[(size_t)G * HH + k + 1];
    } else if (r == 225) {
        if (k < 300)     lo = M[k];
        if (k + 1 < 300) hi = M[k + 1];
    }
    __nv_bfloat162 p = __floats2bfloat162_rn(lo, hi);
    g_Wmma[(size_t)((sr * 15 + w) * 19 + kt) * 128 + l * 4 + j] = *(unsigned*)&p;
}

// ---------------- K0: lengths, attn defaults, aspect mean -> qdot -------------
__global__ void k_init(const int* __restrict__ text, const int* __restrict__ aspi,
                       const int* __restrict__ xl, const int* __restrict__ xr,
                       const float* __restrict__ emb_aspect,
                       const float* __restrict__ w_q, const float* __restrict__ b_q,
                       const float* __restrict__ attn_w,
                       const float* __restrict__ mlp_l_b, const float* __restrict__ mlp_r_b)
{
    int b = blockIdx.x, tid = threadIdx.x;
    int ml = __syncthreads_count(text[b * LL + tid] != 0);
    int ll = __syncthreads_count(xl[b * LL + tid] != 0);
    int rl = __syncthreads_count(xr[b * LL + tid] != 0);
    int al = __syncthreads_count((tid < LAa) && (aspi[b * LAa + tid] != 0));
    if (tid == 0) { g_mem_len[b] = ml; g_left_len[b] = ll; g_right_len[b] = rl; g_asp_len[b] = al; }
    g_attn_l[b * LL + tid] = sigf(mlp_l_b[0]) + 0.5f;
    g_attn_r[b * LL + tid] = sigf(mlp_r_b[0]) + 0.5f;

    __shared__ float s_asp[EE];
    __shared__ float sred[16];
    if (tid < EE) {
        float acc = 0.f;
        #pragma unroll
        for (int a = 0; a < LAa; a++)
            if (a < al) acc += emb_aspect[(size_t)aspi[b * LAa + a] * EE + tid];
        s_asp[tid] = acc / (float)al;
    }
    __syncthreads();
    float val = 0.f;
    if (tid < EE) {
        float acc = b_q[tid];
        const float* wq = w_q + (size_t)tid * EE;
        for (int e = 0; e < EE; e++) acc += s_asp[e] * wq[e];
        val = acc * attn_w[EE + tid];
    }
    #pragma unroll
    for (int o = 16; o > 0; o >>= 1) val += __shfl_xor_sync(0xffffffffu, val, o);
    if ((tid & 31) == 0) sred[tid >> 5] = val;
    __syncthreads();
    if (tid == 0) {
        float s = 0.f;
        #pragma unroll
        for (int w = 0; w < 16; w++) s += sred[w];
        g_qdot[b] = s;
    }
}

// ---------------- K_sched: groups of 4 per side, snake over 32 clusters -------
__global__ void k_sched(const float* __restrict__ b_k, const float* __restrict__ attn_w)
{
    __shared__ float sred[256];
    int i = threadIdx.x;  // 256 threads, 1 block
    float p = 0.f;
    for (int e = i; e < EE; e += 256) p += b_k[e] * attn_w[e];
    sred[i] = p;
    __syncthreads();
    if (i == 0) { float s = 0.f; for (int m = 0; m < 256; m++) s += sred[m]; g_kpad = s; }

    int side = i >> 7, j = i & 127;
    const int* lens = side ? g_right_len : g_left_len;
    int lj = lens[j], r = 0;
    for (int m = 0; m < BB; m++) {
        int lm = lens[m];
        r += (lm > lj) || (lm == lj && m < j);
    }
    int g = side * 32 + (r >> 2);
    g_grp_seq[g][r & 3] = j;
    g_grp_len[g][r & 3] = lj;
    if ((r & 3) == 0) { g_grp_maxlen[g] = lj; g_grp_side[g] = side; }
    __syncthreads();
    if (i < 64) {
        int ml = g_grp_maxlen[i]; int r2 = 0;
        for (int m = 0; m < 64; m++) {
            int lm = g_grp_maxlen[m];
            r2 += (lm > ml) || (lm == ml && m < i);
        }
        int cl = (r2 < 32) ? r2 : 63 - r2;
        g_clu_grp[cl][(r2 < 32) ? 0 : 1] = i;
    }
}

// ---------------- K1: GEMM v7 — fp16 HMMA, structured staging, inline scale ---
__global__ void __launch_bounds__(256, 2) k_gemm3(
    const float* __restrict__ emb, const int* __restrict__ ids,
    const float* __restrict__ W, const float* __restrict__ bias,
    int N, int dst_sel, int limit_sel)
{
    int b = blockIdx.z, m0 = blockIdx.y * 64, n0 = blockIdx.x * 64;
    int lim = (limit_sel == 1) ? g_left_len[b] : (limit_sel == 2) ? g_right_len[b]
            : g_mem_len[b];
    if (m0 >= lim) return;

    float* C = (dst_sel == 0) ? g_xp_l : (dst_sel == 1) ? g_xp_r : g_kx;
    float* Cb = C + (size_t)b * LL * N;
    const int* bids = ids + (size_t)b * LL;

    extern __shared__ __align__(16) __half smem[];
    __half* As = smem;              // [64][312]
    __half* Bs = smem + 64 * 312;   // [64][312]

    int tid = threadIdx.x, lane = tid & 31, wid = tid >> 5;
    int gid = lane >> 2, tig = lane & 3;
    int row = tid >> 2, tpr = tid & 3;

    for (int idx = tid; idx < 64 * 6; idx += 256) {
        int rr = idx / 6, w = idx % 6;
        ((unsigned*)(As + rr * 312))[150 + w] = 0u;
        ((unsigned*)(Bs + rr * 312))[150 + w] = 0u;
    }
    {
        int gm = m0 + row;
        float sc = 1.f;
        if (limit_sel == 3) {
            int ml = g_mem_len[b];
            if (gm < ml) {
                int astart = g_left_len[b] - g_asp_len[b];
                int aend = g_left_len[b];
                float al = g_attn_l[b * LL + gm];
                int ridx = min(max(gm - astart, 0), LL - 1);
                float arv = g_attn_r[b * LL + ridx];
                sc = (gm < astart) ? al : ((gm < aend) ? (al + arv) : arv);
            } else sc = 0.f;
        }
        const float* ar = emb + (size_t)bids[gm] * EE;
        unsigned* dstrow = (unsigned*)(As + row * 312);
        #pragma unroll
        for (int k = 0; k < 19; k++) {
            int c4 = tpr + 4 * k;
            if (c4 < 75) {
                float4 v = *(const float4*)(ar + c4 * 4);
                __half2 p0 = __floats2half2_rn(v.x * sc, v.y * sc);
                __half2 p1 = __floats2half2_rn(v.z * sc, v.w * sc);
                dstrow[c4 * 2]     = *(unsigned*)&p0;
                dstrow[c4 * 2 + 1] = *(unsigned*)&p1;
            }
        }
    }
    {
        int gn = n0 + row;
        const float* br = (gn < N) ? (W + (size_t)gn * EE) : (const float*)0;
        unsigned* dstrow = (unsigned*)(Bs + row * 312);
        #pragma unroll
        for (int k = 0; k < 19; k++) {
            int c4 = tpr + 4 * k;
            if (c4 < 75) {
                if (br) {
                    float4 v = *(const float4*)(br + c4 * 4);
                    __half2 p0 = __floats2half2_rn(v.x, v.y);
                    __half2 p1 = __floats2half2_rn(v.z, v.w);
                    dstrow[c4 * 2]     = *(unsigned*)&p0;
                    dstrow[c4 * 2 + 1] = *(unsigned*)&p1;
                } else {
                    dstrow[c4 * 2] = 0u; dstrow[c4 * 2 + 1] = 0u;
                }
            }
        }
    }
    __syncthreads();

    int wm = wid >> 1, wn = wid & 1;
    const unsigned* A32 = (const unsigned*)As;
    const unsigned* B32 = (const unsigned*)Bs;
    float c[4][4];
    #pragma unroll
    for (int t = 0; t < 4; t++)
        #pragma unroll
        for (int r = 0; r < 4; r++) c[t][r] = 0.f;

    int arow0 = (wm * 16 + gid) * 156;
    int arow1 = arow0 + 8 * 156;
    #pragma unroll
    for (int kt = 0; kt < 19; kt++) {
        int ka = kt * 8 + tig;
        unsigned a0 = A32[arow0 + ka];
        unsigned a1 = A32[arow1 + ka];
        unsigned a2 = A32[arow0 + ka + 4];
        unsigned a3 = A32[arow1 + ka + 4];
        #pragma unroll
        for (int t = 0; t < 4; t++) {
            int nr = (wn * 32 + t * 8 + gid) * 156;
            unsigned b0 = B32[nr + ka];
            unsigned b1 = B32[nr + ka + 4];
            MMAH16816(c[t][0], c[t][1], c[t][2], c[t][3], a0, a1, a2, a3, b0, b1);
        }
    }
    #pragma unroll
    for (int t = 0; t < 4; t++) {
        int on = n0 + wn * 32 + t * 8 + tig * 2;
        int om = m0 + wm * 16 + gid;
        if (on < N) {
            float bi = bias[on];
            Cb[(size_t)om * N + on]       = c[t][0] + bi;
            Cb[(size_t)(om + 8) * N + on] = c[t][2] + bi;
        }
        if (on + 1 < N) {
            float bi = bias[on + 1];
            Cb[(size_t)om * N + on + 1]       = c[t][1] + bi;
            Cb[(size_t)(om + 8) * N + on + 1] = c[t][3] + bi;
        }
    }
}

// ---------------- K2: cluster-4 GRU, bf16 h broadcast, split barrier ----------
__global__ void __launch_bounds__(512, 1) __cluster_dims__(4, 1, 1)
k_gruT(const float* __restrict__ bhh_l, const float* __restrict__ bhh_r,
       const float* __restrict__ mlpb_l, const float* __restrict__ mlpb_r)
{
    __shared__ __align__(16) unsigned hb[2][8 * 156];  // bf16 h, B-frag layout
    __shared__ __align__(16) float s_gate[240][4];

    int tid = threadIdx.x, lane = tid & 31, wid = tid >> 5;
    int gid = lane >> 2, tig = lane & 3;
    unsigned rank = ctarank();
    int c = blockIdx.x >> 2;

    for (int gi = 0; gi < 2; gi++) {
        int grp  = g_clu_grp[c][gi];
        int side = g_grp_side[grp];
        int tmax = g_grp_maxlen[grp];
        const float* bhh  = side ? bhh_r : bhh_l;
        float mbb = side ? mlpb_r[0] : mlpb_l[0];
        const float* xp = side ? g_xp_r : g_xp_l;
        float* attn = side ? g_attn_r : g_attn_l;
        int seqv[4], lenv[4];
        #pragma unroll
        for (int s = 0; s < 4; s++) { seqv[s] = g_grp_seq[grp][s]; lenv[s] = g_grp_len[grp][s]; }

        for (int i = tid; i < 2 * 8 * 156; i += 512) ((unsigned*)hb)[i] = 0u;

        unsigned a[19][4];
        if (wid < 15) {
            const uint4* src = (const uint4*)g_Wmma
                             + (size_t)(((side * 4 + (int)rank) * 15 + wid) * 19) * 32 + lane;
            #pragma unroll
            for (int kt = 0; kt < 19; kt++) {
                uint4 v = src[kt * 32];
                a[kt][0] = v.x; a[kt][1] = v.y; a[kt][2] = v.z; a[kt][3] = v.w;
            }
        }

        int sB = tid / 75, uB = tid % 75, GB = (int)rank * 75 + uB;
        float bhr = 0.f, bhz = 0.f, bhn = 0.f, h_reg = 0.f;
        const float* xpb = 0;
        unsigned ha0 = 0, ha1 = 0;
        if (tid < 300) {
            bhr = bhh[GB]; bhz = bhh[300 + GB]; bhn = bhh[600 + GB];
            xpb = xp + (size_t)seqv[sB] * LL * G3;
            ha0 = smem_u32((const char*)hb[0] + (sB * 312 + GB) * 2);
            ha1 = smem_u32((const char*)hb[1] + (sB * 312 + GB) * 2);
        }
        __syncthreads();
        CLUSTER_SYNC();      // hb zeroed cluster-wide
        CLU_ARRIVE();        // prime first WAIT

        int buf = 0;
        for (int t = 0; t < tmax; t++) {
            CLU_WAIT();      // hb[buf] = h_{t-1} complete everywhere
            float gr = 0.f, gz = 0.f, gn2 = 0.f;
            if (tid < 300) {
                const float* xr = xpb + (size_t)t * G3;
                gr = xr[GB]; gz = xr[300 + GB]; gn2 = xr[600 + GB];
            }
            // tensor GEMV on hb[buf] (rows 0..224 gates; row 225 = wm.h_{t-1})
            if (wid < 15) {
                const unsigned* hp = hb[buf];
                float c0 = 0.f, c1 = 0.f, c2 = 0.f, c3 = 0.f;
                float d0 = 0.f, d1 = 0.f, d2 = 0.f, d3 = 0.f;
                #pragma unroll
                for (int kt = 0; kt < 19; kt += 2) {
                    unsigned b0 = hp[gid * 156 + kt * 8 + tig];
                    unsigned b1 = hp[gid * 156 + kt * 8 + tig + 4];
                    MMA16816(c0, c1, c2, c3, a[kt][0], a[kt][1], a[kt][2], a[kt][3], b0, b1);
                    if (kt + 1 < 19) {
                        unsigned e0 = hp[gid * 156 + (kt + 1) * 8 + tig];
                        unsigned e1 = hp[gid * 156 + (kt + 1) * 8 + tig + 4];
                        MMA16816(d0, d1, d2, d3, a[kt+1][0], a[kt+1][1], a[kt+1][2], a[kt+1][3], e0, e1);
                    }
                }
                c0 += d0; c1 += d1; c2 += d2; c3 += d3;
                if (tig < 2) {
                    int r0 = wid * 16 + gid;
                    *(float2*)&s_gate[r0][2 * tig]     = make_float2(c0, c1);
                    *(float2*)&s_gate[r0 + 8][2 * tig] = make_float2(c2, c3);
                }
            }
            __syncthreads();
            // gate math + bf16 h broadcast into hb[buf^1]
            if (tid < 300) {
                float rp = s_gate[uB][sB];
                float zp = s_gate[75 + uB][sB];
                float np = s_gate[150 + uB][sB];
                float r = fsig(gr + rp + bhr);
                float z = fsig(gz + zp + bhz);
                float n = ftanh(gn2 + r * (np + bhn));
                h_reg = (1.f - z) * n + z * h_reg;
                __nv_bfloat16 hv = __float2bfloat16(h_reg);
                unsigned short bits = *(unsigned short*)&hv;
                unsigned la = buf ? ha0 : ha1;
                #pragma unroll
                for (unsigned rk = 0; rk < 4; rk++) dst_b16(la, rk, bits);
            }
            if (t > 0 && rank == 0 && tid >= 300 && tid < 304) {
                int s = tid - 300;
                if (t - 1 < lenv[s])
                    attn[seqv[s] * LL + (t - 1)] = fsig(s_gate[225][s] + mbb) + 0.5f;
            }
            CLU_ARRIVE();
            buf ^= 1;
        }
        CLU_WAIT();          // hb[buf] = h_{tmax-1}
        // epilogue: row-225 MMA for attn[tmax-1]
        if (wid == 14) {
            const unsigned* hp = hb[buf];
            float c0 = 0.f, c1 = 0.f, c2 = 0.f, c3 = 0.f;
            #pragma unroll
            for (int kt = 0; kt < 19; kt++) {
                unsigned b0 = hp[gid * 156 + kt * 8 + tig];
                unsigned b1 = hp[gid * 156 + kt * 8 + tig + 4];
                MMA16816(c0, c1, c2, c3, a[kt][0], a[kt][1], a[kt][2], a[kt][3], b0, b1);
            }
            if (tig < 2) {
                int r0 = 14 * 16 + gid;
                *(float2*)&s_gate[r0][2 * tig]     = make_float2(c0, c1);
                *(float2*)&s_gate[r0 + 8][2 * tig] = make_float2(c2, c3);
            }
        }
        __syncthreads();
        if (rank == 0 && tid < 4) {
            if (tmax - 1 < lenv[tid])
                attn[seqv[tid] * LL + (tmax - 1)] = fsig(s_gate[225][tid] + mbb) + 0.5f;
        }
        __syncthreads();
        CLUSTER_SYNC();      // all epilogue reads done before next gi re-zeroes hb
    }
}

// ---------------- K4: v_s — parallel scale/id precompute, pipelined gather ----
__global__ void __launch_bounds__(320) k_vs(const int* __restrict__ text,
                                            const float* __restrict__ emb)
{
    __shared__ float s_sc[LL];
    __shared__ int   s_id[LL];
    int b = blockIdx.x, tid = threadIdx.x;
    int ml = g_mem_len[b];
    int astart = g_left_len[b] - g_asp_len[b];
    int aend = g_left_len[b];
    for (int l = tid; l < ml; l += 320) {
        float al = g_attn_l[b * LL + l];
        int ridx = min(max(l - astart, 0), LL - 1);
        float arv = g_attn_r[b * LL + ridx];
        s_sc[l] = (l < astart) ? al : ((l < aend) ? (al + arv) : arv);
        s_id[l] = text[b * LL + l];
    }
    __syncthreads();
    if (tid >= EE) return;
    float acc = 0.f;
    int l = 0;
    for (; l + 4 <= ml; l += 4) {
        float v0 = emb[(size_t)s_id[l]     * EE + tid];
        float v1 = emb[(size_t)s_id[l + 1] * EE + tid];
        float v2 = emb[(size_t)s_id[l + 2] * EE + tid];
        float v3 = emb[(size_t)s_id[l + 3] * EE + tid];
        acc += v0 * s_sc[l] + v1 * s_sc[l + 1] + v2 * s_sc[l + 2] + v3 * s_sc[l + 3];
    }
    for (; l < ml; l++) acc += emb[(size_t)s_id[l] * EE + tid] * s_sc[l];
    g_vs[b * EE + tid] = acc / (float)ml;
}

// ---------------- K5: score->softmax->v_ts->proj->mlp->dense ------------------
__global__ void __launch_bounds__(512) k_tail(
    const float* __restrict__ attn_w, const float* __restrict__ b_k,
    const float* __restrict__ proj_w, const float* __restrict__ proj_b,
    const float* __restrict__ mlp_w, const float* __restrict__ mlp_b,
    const float* __restrict__ dense_w, const float* __restrict__ dense_b,
    float* __restrict__ out)
{
    int b = blockIdx.x, tid = threadIdx.x, lane = tid & 31, wid = tid >> 5;
    __shared__ float s_aw[EE];
    __shared__ float s_sc[LL];
    __shared__ float smax[16], ssum[16];
    __shared__ float s_v[EE], s_v2[EE];
    const float* kxb = g_kx + (size_t)b * LL * EE;
    int ml = g_mem_len[b];
    if (tid < EE) s_aw[tid] = attn_w[tid];
    __syncthreads();
    float qd = g_qdot[b];
    float sc_pad = tanhf(g_kpad + qd);
    for (int l = wid; l < ml; l += 16) {
        const float* row = kxb + (size_t)l * EE;
        float acc = 0.f;
        for (int e = lane; e < EE; e += 32) acc += row[e] * s_aw[e];
        #pragma unroll
        for (int o = 16; o > 0; o >>= 1) acc += __shfl_xor_sync(0xffffffffu, acc, o);
        if (lane == 0) s_sc[l] = tanhf(acc + qd);
    }
    __syncthreads();
    float x = (tid < ml) ? s_sc[tid] : sc_pad;
    float m = x;
    #pragma unroll
    for (int o = 16; o > 0; o >>= 1) m = fmaxf(m, __shfl_xor_sync(0xffffffffu, m, o));
    if (lane == 0) smax[wid] = m;
    __syncthreads();
    float bm = smax[0];
    #pragma unroll
    for (int w = 1; w < 16; w++) bm = fmaxf(bm, smax[w]);
    float p = expf(x - bm);
    float sm = p;
    #pragma unroll
    for (int o = 16; o > 0; o >>= 1) sm += __shfl_xor_sync(0xffffffffu, sm, o);
    if (lane == 0) ssum[wid] = sm;
    __syncthreads();
    float tot = 0.f;
    #pragma unroll
    for (int w = 0; w < 16; w++) tot += ssum[w];
    s_sc[tid] = p / tot;
    __syncthreads();
    float pad_prob = expf(sc_pad - bm) / tot;
    if (tid < EE) {
        float acc = (float)(LL - ml) * pad_prob * b_k[tid];
        for (int l = 0; l < ml; l++) acc += s_sc[l] * kxb[(size_t)l * EE + tid];
        s_v[tid] = acc;
    }
    __syncthreads();
    if (tid < EE) {
        float acc = proj_b[tid];
        const float* w = proj_w + (size_t)tid * EE;
        for (int e = 0; e < EE; e++) acc += s_v[e] * w[e];
        s_v2[tid] = acc + g_vs[b * EE + tid];
    }
    __syncthreads();
    if (tid < EE) {
        float acc = mlp_b[tid];
        const float* w = mlp_w + (size_t)tid * EE;
        for (int e = 0; e < EE; e++) acc += s_v2[e] * w[e];
        s_v[tid] = tanhf(acc);
    }
    __syncthreads();
    if (wid < 3) {
        const float* w = dense_w + (size_t)wid * EE;
        float acc = 0.f;
        for (int e = lane; e < EE; e += 32) acc += s_v[e] * w[e];
        #pragma unroll
        for (int o = 16; o > 0; o >>= 1) acc += __shfl_xor_sync(0xffffffffu, acc, o);
        if (lane == 0) out[b * 3 + wid] = acc + dense_b[wid];
    }
}

extern "C" void kernel_launch(void* const* d_in, const int* in_sizes, int n_in,
                              void* d_out, int out_size)
{
    const int*   text  = (const int*)d_in[0];
    const int*   aspi  = (const int*)d_in[1];
    const int*   xl    = (const int*)d_in[2];
    const int*   xr    = (const int*)d_in[3];
    const float* emb   = (const float*)d_in[4];
    const float* emb_a = (const float*)d_in[5];
    const float* Wih_l = (const float*)d_in[6];
    const float* Whh_l = (const float*)d_in[7];
    const float* bih_l = (const float*)d_in[8];
    const float* bhh_l = (const float*)d_in[9];
    const float* Wih_r = (const float*)d_in[10];
    const float* Whh_r = (const float*)d_in[11];
    const float* bih_r = (const float*)d_in[12];
    const float* bhh_r = (const float*)d_in[13];
    const float* mlw_l = (const float*)d_in[14];
    const float* mlb_l = (const float*)d_in[15];
    const float* mlw_r = (const float*)d_in[16];
    const float* mlb_r = (const float*)d_in[17];
    const float* w_k   = (const float*)d_in[18];
    const float* b_k   = (const float*)d_in[19];
    const float* w_q   = (const float*)d_in[20];
    const float* b_q   = (const float*)d_in[21];
    const float* aw    = (const float*)d_in[22];
    const float* pw    = (const float*)d_in[23];
    const float* pb    = (const float*)d_in[24];
    const float* mw    = (const float*)d_in[25];
    const float* mb    = (const float*)d_in[26];
    const float* dw    = (const float*)d_in[27];
    const float* db    = (const float*)d_in[28];
    float* out = (float*)d_out;

    const int GEMM_SMEM = 2 * 64 * 312 * 2;   // 79872 B -> 2 CTA/SM
    cudaFuncSetAttribute(k_gemm3, cudaFuncAttributeMaxDynamicSharedMemorySize, GEMM_SMEM);

    k_wpk2<<<dim3(285, 8), 128>>>(Whh_l, Whh_r, mlw_l, mlw_r);
    k_init<<<BB, 512>>>(text, aspi, xl, xr, emb_a, w_q, b_q, aw, mlb_l, mlb_r);
    k_sched<<<1, 256>>>(b_k, aw);

    dim3 gx((G3 + 63) / 64, LL / 64, BB);
    k_gemm3<<<gx, 256, GEMM_SMEM>>>(emb, xl, Wih_l, bih_l, G3, 0, 1);
    k_gemm3<<<gx, 256, GEMM_SMEM>>>(emb, xr, Wih_r, bih_r, G3, 1, 2);

    k_gruT<<<BB, 512>>>(bhh_l, bhh_r, mlb_l, mlb_r);

    k_vs<<<BB, 320>>>(text, emb);

    dim3 gk((EE + 63) / 64, LL / 64, BB);
    k_gemm3<<<gk, 256, GEMM_SMEM>>>(emb, text, w_k, b_k, EE, 2, 3);

    k_tail<<<BB, 512>>>(aw, b_k, pw, pb, mw, mb, dw, db, out);
}